// round 14
// baseline (speedup 1.0000x reference)
#include <cuda_runtime.h>
#include <cuda_fp16.h>
#include <math.h>
#include <stdint.h>

#define NG 2048
#define NP 128

// ---------------- scratch (device globals) ----------------
__device__ __half g_hagg[(size_t)NG * NP * 256];    // single fp16 plane
__device__ float g_xin[2 * 1024 * 256];
__device__ float g_out0[2 * 1024 * 32];
__device__ float g_out1[2 * 1024 * 32];
__device__ __half g_w1h[64 * 16],   g_w1l[64 * 16];     // W1^T padded k16
__device__ __half g_w2Th[128 * 64], g_w2Tl[128 * 64];   // edge W2^T
__device__ __half g_nn1Th[96 * 256], g_nn1Tl[96 * 256]; // folded nn1^T
__device__ __half g_nn2Th[64 * 96],  g_nn2Tl[64 * 96];  // nn2^T padded
__device__ float g_nn1bp[96];
__device__ float g_wih0T[256 * 96];

// ---------------- helpers ----------------
__device__ __forceinline__ void splith(float x, __half& h, __half& l) {
    h = __float2half_rn(x);
    l = __float2half_rn(x - __half2float(h));
}
__device__ __forceinline__ uint32_t packh(__half a, __half b) {
    __half2 p = __halves2half2(a, b);
    return *(uint32_t*)&p;
}
__device__ __forceinline__ void splitpack(float x0, float x1, uint32_t& hi, uint32_t& lo) {
    __half h0, l0, h1, l1;
    splith(x0, h0, l0); splith(x1, h1, l1);
    hi = packh(h0, h1); lo = packh(l0, l1);
}
__device__ __forceinline__ uint32_t packf(float x0, float x1) {
    return packh(__float2half_rn(x0), __float2half_rn(x1));
}
__device__ __forceinline__ void mma16(float d[4], const uint32_t a[4], const uint32_t b[2]) {
    asm volatile(
        "mma.sync.aligned.m16n8k16.row.col.f32.f16.f16.f32 "
        "{%0,%1,%2,%3},{%4,%5,%6,%7},{%8,%9},{%0,%1,%2,%3};"
        : "+f"(d[0]), "+f"(d[1]), "+f"(d[2]), "+f"(d[3])
        : "r"(a[0]), "r"(a[1]), "r"(a[2]), "r"(a[3]), "r"(b[0]), "r"(b[1]));
}
__device__ __forceinline__ void mma3h(float d[4], const uint32_t ah[4], const uint32_t al[4],
                                      const uint32_t bh[2], const uint32_t bl[2]) {
    mma16(d, ah, bh); mma16(d, ah, bl); mma16(d, al, bh);
}
__device__ __forceinline__ void mma2h(float d[4], const uint32_t ah[4],
                                      const uint32_t bh[2], const uint32_t bl[2]) {
    mma16(d, ah, bh); mma16(d, ah, bl);
}
// ldmatrix x4 (A m16k16 frag, or B-pair load). stride in halves (16B-mult rows).
__device__ __forceinline__ void ldsm4(const __half* P, int strideH, int m0, int k0, int lid, uint32_t a[4]) {
    uint32_t addr = (uint32_t)__cvta_generic_to_shared(
        P + (size_t)(m0 + (lid & 15)) * strideH + k0 + ((lid >> 4) << 3));
    asm volatile("ldmatrix.sync.aligned.m8n8.x4.shared.b16 {%0,%1,%2,%3}, [%4];"
        : "=r"(a[0]), "=r"(a[1]), "=r"(a[2]), "=r"(a[3]) : "r"(addr));
}

// ---------------- weight prep: pre-split hi/lo half planes ----------------
__global__ void prep_kernel(const float* __restrict__ nn1W, const float* __restrict__ nn1b,
                            const float* __restrict__ nn2W, const float* __restrict__ W2,
                            const float* __restrict__ W1, const float* __restrict__ wih0)
{
    int idx = blockIdx.x * 256 + threadIdx.x;   // 96 blocks -> 24576
    __half h, l;
    if (idx < 64 * 16) {
        int n = idx >> 4, k = idx & 15;
        float v = (k < 10) ? W1[k * 64 + n] : 0.f;
        splith(v, h, l); g_w1h[idx] = h; g_w1l[idx] = l;
    }
    if (idx < 128 * 64) {
        int n = idx >> 6, k = idx & 63;
        splith(W2[k * 128 + n], h, l); g_w2Th[idx] = h; g_w2Tl[idx] = l;
    }
    if (idx < 96 * 256) {
        int n = idx >> 8, k = idx & 255;
        float v = 0.f;
        if (n < 94) {
            if (k < 128) v = nn1W[k * 94 + n];
            else { int kk = k - 128; v = 0.25f * nn1W[(128 + kk) * 94 + n] + nn1W[(256 + kk) * 94 + n]; }
        }
        splith(v, h, l); g_nn1Th[idx] = h; g_nn1Tl[idx] = l;
    }
    if (idx < 64 * 96) {
        int n = idx / 96, k = idx % 96;
        float v = (k < 94) ? nn2W[k * 64 + n] : 0.f;
        splith(v, h, l); g_nn2Th[idx] = h; g_nn2Tl[idx] = l;
    }
    if (idx < 96) g_nn1bp[idx] = (idx < 94) ? nn1b[idx] : 0.f;
    if (idx < 96 * 256) { int gg = idx >> 8, d = idx & 255; g_wih0T[d * 96 + gg] = wih0[idx]; }
}

// ================= EC kernel: KNN + EdgeConv, register-chained l1->l2 =================
#define EC_XS    0        // 2560
#define EC_NBR   2560     // 2048
#define EC_W1H   4608     // [64][24] half = 3072
#define EC_W1L   7680     // 3072
#define EC_B1    10752    // 256
#define EC_B2    11008    // 512
#define EC_W2H   11520    // [128][72] half = 18432
#define EC_W2L   29952    // 18432
#define EC_SMEM  48384

__global__ void __launch_bounds__(256, 2) ec_kernel(
    const float* __restrict__ x, const float* __restrict__ b1, const float* __restrict__ b2)
{
    extern __shared__ __align__(16) char smem[];
    float* xs   = (float*)(smem + EC_XS);
    int*   nbr  = (int*)(smem + EC_NBR);
    __half* W1H = (__half*)(smem + EC_W1H);
    __half* W1L = (__half*)(smem + EC_W1L);
    float* b1s  = (float*)(smem + EC_B1);
    float* b2s  = (float*)(smem + EC_B2);
    __half* W2H = (__half*)(smem + EC_W2H);
    __half* W2L = (__half*)(smem + EC_W2L);

    const int tid = threadIdx.x, wid = tid >> 5, lid = tid & 31;
    const int qr = lid >> 2, qc = lid & 3;
    const int g = blockIdx.x;
    const size_t base = (size_t)g * NP;

    for (int i = tid; i < NP * 5; i += 256) xs[i] = x[base * 5 + i];
    for (int i = tid; i < 512; i += 256) {
        int n = i >> 3, kw = i & 7;
        ((uint32_t*)W1H)[n * 12 + kw] = ((const uint32_t*)g_w1h)[i];
        ((uint32_t*)W1L)[n * 12 + kw] = ((const uint32_t*)g_w1l)[i];
    }
    if (tid < 64) b1s[tid] = b1[tid];
    if (tid >= 64 && tid < 192) b2s[tid - 64] = b2[tid - 64];
    for (int i = tid; i < 4096; i += 256) {
        int n = i >> 5, kw = i & 31;
        ((uint32_t*)W2H)[n * 36 + kw] = ((const uint32_t*)g_w2Th)[i];
        ((uint32_t*)W2L)[n * 36 + kw] = ((const uint32_t*)g_w2Tl)[i];
    }
    __syncthreads();

    // ---- KNN (thread = node), branchless, stable ties
    if (tid < NP) {
        const float px = xs[tid * 5 + 0], py = xs[tid * 5 + 1], pz = xs[tid * 5 + 2];
        float d0 = 1e30f, d1 = 1e30f, d2v = 1e30f, d3 = 1e30f;
        int i0 = 0, i1 = 0, i2 = 0, i3 = 0;
#pragma unroll 4
        for (int j = 0; j < NP; j++) {
            float dx = xs[j * 5 + 0] - px, dy = xs[j * 5 + 1] - py, dz = xs[j * 5 + 2] - pz;
            float dd = dx * dx + dy * dy + dz * dz;
            dd = (j == tid) ? 1e30f : dd;
            bool c0 = dd < d0, c1 = dd < d1, c2 = dd < d2v, c3 = dd < d3;
            i3 = c2 ? i2 : (c3 ? j : i3);  d3  = c2 ? d2v : (c3 ? dd : d3);
            i2 = c1 ? i1 : (c2 ? j : i2);  d2v = c1 ? d1  : (c2 ? dd : d2v);
            i1 = c0 ? i0 : (c1 ? j : i1);  d1  = c0 ? d0  : (c1 ? dd : d1);
            i0 = c0 ? j : i0;              d0  = c0 ? dd  : d0;
        }
        nbr[tid * 4 + 0] = i0; nbr[tid * 4 + 1] = i1; nbr[tid * 4 + 2] = i2; nbr[tid * 4 + 3] = i3;
    }
    __syncthreads();

    // ---- main loop: warp-independent 16-edge tiles, NO block syncs
    for (int it = 0; it < 4; it++) {
        const int tile = it * 8 + wid;
        const int node = tile * 4 + (qr & 3);
        const int kb = (qr >> 2) & 1;
        const int j0 = nbr[node * 4 + kb];
        const int j1 = nbr[node * 4 + kb + 2];

        // edge features in registers -> l1 A-frag (split x3 for layer-1)
        uint32_t a1h[4], a1l[4];
        {
            const int d0 = 2 * qc, d2 = 8 + 2 * qc;
            float f0, f1, f2, f3, f4, f5, f6, f7;
            if (d0 < 5) { f0 = xs[node * 5 + d0]; f2 = f0; }
            else        { f0 = xs[j0 * 5 + d0 - 5] - xs[node * 5 + d0 - 5];
                          f2 = xs[j1 * 5 + d0 - 5] - xs[node * 5 + d0 - 5]; }
            if (d0 + 1 < 5) { f1 = xs[node * 5 + d0 + 1]; f3 = f1; }
            else            { f1 = xs[j0 * 5 + d0 - 4] - xs[node * 5 + d0 - 4];
                              f3 = xs[j1 * 5 + d0 - 4] - xs[node * 5 + d0 - 4]; }
            if (d2 < 10) {
                f4 = xs[j0 * 5 + 3] - xs[node * 5 + 3];
                f5 = xs[j0 * 5 + 4] - xs[node * 5 + 4];
                f6 = xs[j1 * 5 + 3] - xs[node * 5 + 3];
                f7 = xs[j1 * 5 + 4] - xs[node * 5 + 4];
            } else { f4 = 0.f; f5 = 0.f; f6 = 0.f; f7 = 0.f; }
            splitpack(f0, f1, a1h[0], a1l[0]);
            splitpack(f2, f3, a1h[1], a1l[1]);
            splitpack(f4, f5, a1h[2], a1l[2]);
            splitpack(f6, f7, a1h[3], a1l[3]);
        }

        // layer-1: 8 nt (64 cols), K=16, x3
        float acc1[8][4];
#pragma unroll
        for (int j = 0; j < 8; j++) { acc1[j][0]=0.f; acc1[j][1]=0.f; acc1[j][2]=0.f; acc1[j][3]=0.f; }
#pragma unroll
        for (int jp = 0; jp < 4; jp++) {
            uint32_t bh4[4], bl4[4];
            ldsm4(W1H, 24, jp * 16, 0, lid, bh4);
            ldsm4(W1L, 24, jp * 16, 0, lid, bl4);
            uint32_t b0h[2] = {bh4[0], bh4[2]}, b1h[2] = {bh4[1], bh4[3]};
            uint32_t b0l[2] = {bl4[0], bl4[2]}, b1l[2] = {bl4[1], bl4[3]};
            mma3h(acc1[jp * 2],     a1h, a1l, b0h, b0l);
            mma3h(acc1[jp * 2 + 1], a1h, a1l, b1h, b1l);
        }

        // layer-2: A plain fp16 from acc1 (bias+relu in regs), 16 nt, K=64, x2
        float acc2[16][4];
#pragma unroll
        for (int j = 0; j < 16; j++) { acc2[j][0]=0.f; acc2[j][1]=0.f; acc2[j][2]=0.f; acc2[j][3]=0.f; }
#pragma unroll
        for (int ks = 0; ks < 4; ks++) {
            uint32_t a2[4];
            {
                const int c0 = (2 * ks) * 8 + 2 * qc;
                const int c2 = (2 * ks + 1) * 8 + 2 * qc;
                float v0 = fmaxf(acc1[2 * ks][0] + b1s[c0], 0.f);
                float v1 = fmaxf(acc1[2 * ks][1] + b1s[c0 + 1], 0.f);
                float v2 = fmaxf(acc1[2 * ks][2] + b1s[c0], 0.f);
                float v3 = fmaxf(acc1[2 * ks][3] + b1s[c0 + 1], 0.f);
                float v4 = fmaxf(acc1[2 * ks + 1][0] + b1s[c2], 0.f);
                float v5 = fmaxf(acc1[2 * ks + 1][1] + b1s[c2 + 1], 0.f);
                float v6 = fmaxf(acc1[2 * ks + 1][2] + b1s[c2], 0.f);
                float v7 = fmaxf(acc1[2 * ks + 1][3] + b1s[c2 + 1], 0.f);
                a2[0] = packf(v0, v1); a2[1] = packf(v2, v3);
                a2[2] = packf(v4, v5); a2[3] = packf(v6, v7);
            }
#pragma unroll
            for (int jp = 0; jp < 8; jp++) {
                uint32_t bh4[4], bl4[4];
                ldsm4(W2H, 72, jp * 16, ks * 16, lid, bh4);
                ldsm4(W2L, 72, jp * 16, ks * 16, lid, bl4);
                uint32_t b0h[2] = {bh4[0], bh4[2]}, b1h[2] = {bh4[1], bh4[3]};
                uint32_t b0l[2] = {bl4[0], bl4[2]}, b1l[2] = {bl4[1], bl4[3]};
                mma2h(acc2[jp * 2],     a2, b0h, b0l);
                mma2h(acc2[jp * 2 + 1], a2, b1h, b1l);
            }
        }

        // epilogue: +b2, relu; in-thread k={kb,kb+2}; XOR-16 pairs kb<->kb^1; fp16 store
        {
            uint32_t* Gh = (uint32_t*)g_hagg + (base + node) * 128;
#pragma unroll
            for (int j = 0; j < 16; j++) {
                const int col = j * 8 + 2 * qc;
                float v0 = fmaxf(acc2[j][0] + b2s[col], 0.f);
                float v1 = fmaxf(acc2[j][1] + b2s[col + 1], 0.f);
                float v2 = fmaxf(acc2[j][2] + b2s[col], 0.f);
                float v3 = fmaxf(acc2[j][3] + b2s[col + 1], 0.f);
                float mx0 = fmaxf(v0, v2), mx1 = fmaxf(v1, v3);
                float sm0 = v0 + v2,       sm1 = v1 + v3;
                mx0 = fmaxf(mx0, __shfl_xor_sync(0xffffffffu, mx0, 16));
                mx1 = fmaxf(mx1, __shfl_xor_sync(0xffffffffu, mx1, 16));
                sm0 += __shfl_xor_sync(0xffffffffu, sm0, 16);
                sm1 += __shfl_xor_sync(0xffffffffu, sm1, 16);
                if ((qr < 4) == (j < 8)) {
                    Gh[col >> 1]        = packf(mx0, mx1);
                    Gh[64 + (col >> 1)] = packf(sm0, sm1);
                }
            }
        }
    }
}

// ================= NN kernel: nn1(x2) + nn2(x2) + segreduce -> g_xin =================
#define NN_ASH  0         // A chunk [128][40] half = 10240
#define NN_B1H  10240     // [96][40] half = 7680
#define NN_B1L  17920     // 7680 -> end 25600
#define NN_B2H  0         // overlay after nn1: [64][104] half = 13312
#define NN_B2L  13312     // 13312 -> end 26624
#define NN_H2H  26624     // [128][104] half = 26624 (h2 fp32 [128][68] overlays after nn2)
#define NN_RED  61440     // 3072
#define NN_B1V  64512     // 384
#define NN_B2V  64896     // 256
#define NN_SMEM 65152

__global__ void __launch_bounds__(256, 2) nn_kernel(const float* __restrict__ nn2b)
{
    extern __shared__ __align__(16) char smem[];
    __half* AsH = (__half*)(smem + NN_ASH);
    __half* B1H = (__half*)(smem + NN_B1H);
    __half* B1L = (__half*)(smem + NN_B1L);
    __half* B2H = (__half*)(smem + NN_B2H);
    __half* B2L = (__half*)(smem + NN_B2L);
    __half* H2H = (__half*)(smem + NN_H2H);
    float* red  = (float*)(smem + NN_RED);
    float* b1v  = (float*)(smem + NN_B1V);
    float* b2v  = (float*)(smem + NN_B2V);

    const int tid = threadIdx.x, wid = tid >> 5, lid = tid & 31;
    const int rw = wid >> 1, nh = wid & 1;
    const int qr = lid >> 2, qc = lid & 3;
    const int g = blockIdx.x;
    const __half* Ah = g_hagg + (size_t)g * NP * 256;

    if (tid < 96) b1v[tid] = g_nn1bp[tid];
    if (tid >= 96 && tid < 160) b2v[tid - 96] = nn2b[tid - 96];

    // ---- nn1: [128][256] @ [256][96]; A plain fp16, x2
    float acc1[2][6][4];
#pragma unroll
    for (int rt = 0; rt < 2; rt++)
#pragma unroll
        for (int j = 0; j < 6; j++) { acc1[rt][j][0]=0.f; acc1[rt][j][1]=0.f; acc1[rt][j][2]=0.f; acc1[rt][j][3]=0.f; }
    for (int kc = 0; kc < 8; kc++) {
        for (int i = tid; i < 512; i += 256) {
            int r = i >> 2, q = i & 3;
            *(uint4*)(AsH + r * 40 + q * 8) = *(const uint4*)(Ah + r * 256 + kc * 32 + q * 8);
        }
        for (int i = tid; i < 1536; i += 256) {
            int n = i >> 4, kw = i & 15;
            ((uint32_t*)B1H)[n * 20 + kw] = ((const uint32_t*)g_nn1Th)[n * 128 + kc * 16 + kw];
            ((uint32_t*)B1L)[n * 20 + kw] = ((const uint32_t*)g_nn1Tl)[n * 128 + kc * 16 + kw];
        }
        __syncthreads();
#pragma unroll
        for (int ks = 0; ks < 2; ks++) {
            uint32_t ah[2][4];
            ldsm4(AsH, 40, rw * 32,      ks * 16, lid, ah[0]);
            ldsm4(AsH, 40, rw * 32 + 16, ks * 16, lid, ah[1]);
#pragma unroll
            for (int jp = 0; jp < 3; jp++) {
                uint32_t bh4[4], bl4[4];
                ldsm4(B1H, 40, (nh * 6 + jp * 2) * 8, ks * 16, lid, bh4);
                ldsm4(B1L, 40, (nh * 6 + jp * 2) * 8, ks * 16, lid, bl4);
                uint32_t b0h[2] = {bh4[0], bh4[2]}, b1h[2] = {bh4[1], bh4[3]};
                uint32_t b0l[2] = {bl4[0], bl4[2]}, b1l[2] = {bl4[1], bl4[3]};
                mma2h(acc1[0][jp * 2],     ah[0], b0h, b0l);
                mma2h(acc1[1][jp * 2],     ah[1], b0h, b0l);
                mma2h(acc1[0][jp * 2 + 1], ah[0], b1h, b1l);
                mma2h(acc1[1][jp * 2 + 1], ah[1], b1h, b1l);
            }
        }
        __syncthreads();
    }
    // epilogue1: H2 plain fp16 = relu(acc1 + b1v); stage B2 planes (overlay A/B1)
    {
#pragma unroll
        for (int rt = 0; rt < 2; rt++) {
            int r0 = rw * 32 + rt * 16 + qr, r1 = r0 + 8;
#pragma unroll
            for (int j = 0; j < 6; j++) {
                int col = (nh * 6 + j) * 8 + 2 * qc;
                float v0 = fmaxf(acc1[rt][j][0] + b1v[col], 0.f), v1 = fmaxf(acc1[rt][j][1] + b1v[col + 1], 0.f);
                float v2 = fmaxf(acc1[rt][j][2] + b1v[col], 0.f), v3 = fmaxf(acc1[rt][j][3] + b1v[col + 1], 0.f);
                ((uint32_t*)H2H)[r0 * 52 + (col >> 1)] = packf(v0, v1);
                ((uint32_t*)H2H)[r1 * 52 + (col >> 1)] = packf(v2, v3);
            }
        }
        for (int i = tid; i < 3072; i += 256) {
            int n = i / 48, kw = i % 48;
            ((uint32_t*)B2H)[n * 52 + kw] = ((const uint32_t*)g_nn2Th)[n * 48 + kw];
            ((uint32_t*)B2L)[n * 52 + kw] = ((const uint32_t*)g_nn2Tl)[n * 48 + kw];
        }
    }
    __syncthreads();

    // ---- nn2: [128][96] @ [96][64], K=96, x2 (A plain fp16)
    float acc2[2][4][4];
#pragma unroll
    for (int rt = 0; rt < 2; rt++)
#pragma unroll
        for (int j = 0; j < 4; j++) { acc2[rt][j][0]=0.f; acc2[rt][j][1]=0.f; acc2[rt][j][2]=0.f; acc2[rt][j][3]=0.f; }
#pragma unroll
    for (int ks = 0; ks < 6; ks++) {
        uint32_t ah[2][4];
        ldsm4(H2H, 104, rw * 32,      ks * 16, lid, ah[0]);
        ldsm4(H2H, 104, rw * 32 + 16, ks * 16, lid, ah[1]);
#pragma unroll
        for (int jp = 0; jp < 2; jp++) {
            uint32_t bh4[4], bl4[4];
            ldsm4(B2H, 104, (nh * 4 + jp * 2) * 8, ks * 16, lid, bh4);
            ldsm4(B2L, 104, (nh * 4 + jp * 2) * 8, ks * 16, lid, bl4);
            uint32_t b0h[2] = {bh4[0], bh4[2]}, b1h[2] = {bh4[1], bh4[3]};
            uint32_t b0l[2] = {bl4[0], bl4[2]}, b1l[2] = {bl4[1], bl4[3]};
            mma2h(acc2[0][jp * 2],     ah[0], b0h, b0l);
            mma2h(acc2[1][jp * 2],     ah[1], b0h, b0l);
            mma2h(acc2[0][jp * 2 + 1], ah[0], b1h, b1l);
            mma2h(acc2[1][jp * 2 + 1], ah[1], b1h, b1l);
        }
    }
    __syncthreads();
    float* h2 = (float*)(smem + NN_H2H);          // [128][68] fp32 overlay
    {
#pragma unroll
        for (int rt = 0; rt < 2; rt++) {
            int r0 = rw * 32 + rt * 16 + qr, r1 = r0 + 8;
#pragma unroll
            for (int j = 0; j < 4; j++) {
                int col = (nh * 4 + j) * 8 + 2 * qc;
                float2 u0 = { acc2[rt][j][0] + b2v[col], acc2[rt][j][1] + b2v[col + 1] };
                float2 u1 = { acc2[rt][j][2] + b2v[col], acc2[rt][j][3] + b2v[col + 1] };
                *(float2*)&h2[r0 * 68 + col] = u0;
                *(float2*)&h2[r1 * 68 + col] = u1;
            }
        }
    }
    __syncthreads();

    // ---- segment max/min/sum/mean + relu -> g_xin (permute fused)
    {
        int c = tid & 63, q = tid >> 6;
        float mx = -1e30f, mn = 1e30f, sm = 0.f;
        for (int r = q * 32; r < q * 32 + 32; r++) {
            float v = h2[r * 68 + c];
            mx = fmaxf(mx, v); mn = fminf(mn, v); sm += v;
        }
        red[q * 192 + c] = mx; red[q * 192 + 64 + c] = mn; red[q * 192 + 128 + c] = sm;
        __syncthreads();
        if (tid < 64) {
            float MX = red[c], MN = red[64 + c], SM = red[128 + c];
            for (int qq = 1; qq < 4; qq++) {
                MX = fmaxf(MX, red[qq * 192 + c]);
                MN = fminf(MN, red[qq * 192 + 64 + c]);
                SM += red[qq * 192 + 128 + c];
            }
            const int t = g >> 10, qg = g & 1023;
            const int i = qg >> 2;
            float* xrow = g_xin + ((size_t)((t << 10) + (qg & 3) * 256) << 8) + i;
            xrow[(size_t)c * 256]         = fmaxf(MX, 0.f);
            xrow[(size_t)(64 + c) * 256]  = fmaxf(MN, 0.f);
            xrow[(size_t)(128 + c) * 256] = fmaxf(SM, 0.f);
            xrow[(size_t)(192 + c) * 256] = fmaxf(SM * (1.f / 128.f), 0.f);
        }
    }
}

// ================= fused GRU (GI gemm folded in): warp = row =================
#define GR_W0   0          // 96*33*4 = 12672
#define GR_W1   12672      // 12672
#define GR_WI1  25344      // 12672 -> end 38016
#define GR_WIH  38016      // 256*96*4 = 98304 -> end 136320
#define GR_XS   136320     // 32*260*4 = 33280 -> end 169600
#define GR_SMEM 169600

__global__ void __launch_bounds__(512) gru_all_kernel(
    const float* __restrict__ h1in,
    const float* __restrict__ wih0T, const float* __restrict__ bih0,
    const float* __restrict__ wih1, const float* __restrict__ bih1,
    const float* __restrict__ whh0, const float* __restrict__ bhh0,
    const float* __restrict__ whh1, const float* __restrict__ bhh1)
{
    extern __shared__ __align__(16) char smem[];
    float (*w0)[33]  = (float(*)[33])(smem + GR_W0);
    float (*w1)[33]  = (float(*)[33])(smem + GR_W1);
    float (*wi1)[33] = (float(*)[33])(smem + GR_WI1);
    float* Wih       = (float*)(smem + GR_WIH);      // [256][96]
    float (*xsr)[260] = (float(*)[260])(smem + GR_XS);

    const int tid = threadIdx.x;
    const int wr = tid >> 5, u = tid & 31;
    const int row0 = blockIdx.x * 16;
    const int row = row0 + wr;

    for (int i = tid; i < 3072; i += 512) {
        w0[i >> 5][i & 31] = whh0[i];
        w1[i >> 5][i & 31] = whh1[i];
        wi1[i >> 5][i & 31] = wih1[i];
    }
    for (int i = tid; i < 24576; i += 512) Wih[i] = wih0T[i];
    for (int i = tid; i < 8192; i += 512) {
        int r2 = i >> 8, d = i & 255;
        int grow = ((r2 >= 16) ? 1024 : 0) + row0 + (r2 & 15);
        xsr[r2][d] = g_xin[(size_t)grow * 256 + d];
    }
    __syncthreads();

    // GI for this (row, u): 3 gates x 2 timesteps
    float gi0r, gi0z, gi0n, gi1r, gi1z, gi1n;
    {
        const float br = bih0[u], bz = bih0[32 + u], bn = bih0[64 + u];
        float a0 = br, a1 = bz, a2 = bn;
        float c0 = br, c1 = bz, c2 = bn;
        const float* x0 = xsr[wr];
        const float* x1 = xsr[16 + wr];
#pragma unroll 8
        for (int d = 0; d < 256; d++) {
            const float w_r = Wih[d * 96 + u];
            const float w_z = Wih[d * 96 + 32 + u];
            const float w_n = Wih[d * 96 + 64 + u];
            const float v0 = x0[d], v1 = x1[d];
            a0 = fmaf(v0, w_r, a0); a1 = fmaf(v0, w_z, a1); a2 = fmaf(v0, w_n, a2);
            c0 = fmaf(v1, w_r, c0); c1 = fmaf(v1, w_z, c1); c2 = fmaf(v1, w_n, c2);
        }
        gi0r = a0; gi0z = a1; gi0n = a2;
        gi1r = c0; gi1z = c1; gi1n = c2;
    }

    float h0 = h1in[row * 32 + u];
    float hv1 = h1in[32768 + row * 32 + u];
    const float b0r = bhh0[u], b0z = bhh0[32 + u], b0n = bhh0[64 + u];
    const float bi1r = bih1[u], bi1z = bih1[32 + u], bi1n = bih1[64 + u];
    const float b1r = bhh1[u], b1z = bhh1[32 + u], b1n = bhh1[64 + u];

#pragma unroll
    for (int t = 0; t < 2; t++) {
        float gr = t ? gi1r : gi0r, gz = t ? gi1z : gi0z, gn = t ? gi1n : gi0n;
        float hr = b0r, hz = b0z, hn = b0n;
#pragma unroll
        for (int d = 0; d < 32; d++) {
            float hv = __shfl_sync(0xffffffffu, h0, d);
            hr = fmaf(hv, w0[u][d], hr);
            hz = fmaf(hv, w0[32 + u][d], hz);
            hn = fmaf(hv, w0[64 + u][d], hn);
        }
        float rr = 1.f / (1.f + expf(-(gr + hr)));
        float zz = 1.f / (1.f + expf(-(gz + hz)));
        float nn = tanhf(gn + rr * hn);
        h0 = (1.f - zz) * nn + zz * h0;

        float xr = bi1r, xz = bi1z, xn = bi1n;
        float yr = b1r, yz = b1z, yn = b1n;
#pragma unroll
        for (int d = 0; d < 32; d++) {
            float xv = __shfl_sync(0xffffffffu, h0, d);
            xr = fmaf(xv, wi1[u][d], xr);
            xz = fmaf(xv, wi1[32 + u][d], xz);
            xn = fmaf(xv, wi1[64 + u][d], xn);
            float hv = __shfl_sync(0xffffffffu, hv1, d);
            yr = fmaf(hv, w1[u][d], yr);
            yz = fmaf(hv, w1[32 + u][d], yz);
            yn = fmaf(hv, w1[64 + u][d], yn);
        }
        float r1 = 1.f / (1.f + expf(-(xr + yr)));
        float z1 = 1.f / (1.f + expf(-(xz + yz)));
        float n1 = tanhf(xn + r1 * yn);
        hv1 = (1.f - z1) * n1 + z1 * hv1;
        g_out1[t * 32768 + row * 32 + u] = hv1;
    }
    g_out0[32768 + row * 32 + u] = h0;   // hT of layer 0
}

// ---------------- final head + hT pack ----------------
__global__ void final_kernel(const float* __restrict__ nn4W, const float* __restrict__ nn4b,
                             float* __restrict__ out, int out_size)
{
    const int idx = blockIdx.x * 256 + threadIdx.x;
    if (idx >= out_size) return;
    if (idx < 2048) {
        const int t  = idx >> 10;
        const int ch = (idx >> 5) & 31;
        const int b0 = (idx & 31) * 32;
        float acc = nn4b[0];
#pragma unroll
        for (int c = 0; c < 32; c++) {
            const float v = g_out1[t * 32768 + (b0 + c) * 32 + ch];
            acc = fmaf(fmaxf(v, 0.f), nn4W[c], acc);
        }
        out[idx] = fmaxf(acc, 0.f);
    } else if (idx < 2048 + 65536) {
        const int j = idx - 2048;
        out[idx] = (j < 32768) ? g_out0[32768 + j] : g_out1[32768 + (j - 32768)];
    }
}

// ---------------- launch ----------------
extern "C" void kernel_launch(void* const* d_in, const int* in_sizes, int n_in,
                              void* d_out, int out_size)
{
    const float* x    = (const float*)d_in[0];
    const float* h1   = (const float*)d_in[2];
    const float* W1   = (const float*)d_in[3];
    const float* b1   = (const float*)d_in[4];
    const float* W2   = (const float*)d_in[5];
    const float* b2   = (const float*)d_in[6];
    const float* nn1W = (const float*)d_in[7];
    const float* nn1b = (const float*)d_in[8];
    const float* nn2W = (const float*)d_in[9];
    const float* nn2b = (const float*)d_in[10];
    const float* nn4W = (const float*)d_in[11];
    const float* nn4b = (const float*)d_in[12];
    const float* wih0 = (const float*)d_in[13];
    const float* whh0 = (const float*)d_in[14];
    const float* bih0 = (const float*)d_in[15];
    const float* bhh0 = (const float*)d_in[16];
    const float* wih1 = (const float*)d_in[17];
    const float* whh1 = (const float*)d_in[18];
    const float* bih1 = (const float*)d_in[19];
    const float* bhh1 = (const float*)d_in[20];
    float* out = (float*)d_out;

    float* wih0T;
    cudaGetSymbolAddress((void**)&wih0T, g_wih0T);

    cudaFuncSetAttribute(ec_kernel,      cudaFuncAttributeMaxDynamicSharedMemorySize, EC_SMEM);
    cudaFuncSetAttribute(nn_kernel,      cudaFuncAttributeMaxDynamicSharedMemorySize, NN_SMEM);
    cudaFuncSetAttribute(gru_all_kernel, cudaFuncAttributeMaxDynamicSharedMemorySize, GR_SMEM);

    prep_kernel<<<96, 256>>>(nn1W, nn1b, nn2W, W2, W1, wih0);
    ec_kernel<<<NG, 256, EC_SMEM>>>(x, b1, b2);
    nn_kernel<<<NG, 256, NN_SMEM>>>(nn2b);
    gru_all_kernel<<<64, 512, GR_SMEM>>>(h1, wih0T, bih0, wih1, bih1, whh0, bhh0, whh1, bhh1);
    final_kernel<<<(out_size + 255) / 256, 256>>>(nn4W, nn4b, out, out_size);
}

// round 15
// speedup vs baseline: 1.4451x; 1.4451x over previous
#include <cuda_runtime.h>
#include <cuda_fp16.h>
#include <math.h>
#include <stdint.h>

#define NG 2048
#define NP 128

// ---------------- scratch (device globals) ----------------
__device__ __half g_hagg[(size_t)NG * NP * 256];    // single fp16 plane
__device__ float g_xin[2 * 1024 * 256];
__device__ float g_gi[2 * 1024 * 96];
__device__ float g_out0[2 * 1024 * 32];
__device__ float g_out1[2 * 1024 * 32];
__device__ __half g_w1h[64 * 16],   g_w1l[64 * 16];     // W1^T padded k16
__device__ __half g_w2Th[128 * 64], g_w2Tl[128 * 64];   // edge W2^T
__device__ __half g_nn1Th[96 * 256], g_nn1Tl[96 * 256]; // folded nn1^T
__device__ __half g_nn2Th[64 * 96],  g_nn2Tl[64 * 96];  // nn2^T padded
__device__ float g_nn1bp[96];
__device__ float g_wih0T[256 * 96];

// ---------------- helpers ----------------
__device__ __forceinline__ void splith(float x, __half& h, __half& l) {
    h = __float2half_rn(x);
    l = __float2half_rn(x - __half2float(h));
}
__device__ __forceinline__ uint32_t packh(__half a, __half b) {
    __half2 p = __halves2half2(a, b);
    return *(uint32_t*)&p;
}
__device__ __forceinline__ void splitpack(float x0, float x1, uint32_t& hi, uint32_t& lo) {
    __half h0, l0, h1, l1;
    splith(x0, h0, l0); splith(x1, h1, l1);
    hi = packh(h0, h1); lo = packh(l0, l1);
}
__device__ __forceinline__ uint32_t packf(float x0, float x1) {
    return packh(__float2half_rn(x0), __float2half_rn(x1));
}
__device__ __forceinline__ void mma16(float d[4], const uint32_t a[4], const uint32_t b[2]) {
    asm volatile(
        "mma.sync.aligned.m16n8k16.row.col.f32.f16.f16.f32 "
        "{%0,%1,%2,%3},{%4,%5,%6,%7},{%8,%9},{%0,%1,%2,%3};"
        : "+f"(d[0]), "+f"(d[1]), "+f"(d[2]), "+f"(d[3])
        : "r"(a[0]), "r"(a[1]), "r"(a[2]), "r"(a[3]), "r"(b[0]), "r"(b[1]));
}
__device__ __forceinline__ void mma3h(float d[4], const uint32_t ah[4], const uint32_t al[4],
                                      const uint32_t bh[2], const uint32_t bl[2]) {
    mma16(d, ah, bh); mma16(d, ah, bl); mma16(d, al, bh);
}
__device__ __forceinline__ void mma2h(float d[4], const uint32_t ah[4],
                                      const uint32_t bh[2], const uint32_t bl[2]) {
    mma16(d, ah, bh); mma16(d, ah, bl);
}
// ldmatrix x4 (A m16k16 frag, or B-pair load). stride in halves (16B-mult rows).
__device__ __forceinline__ void ldsm4(const __half* P, int strideH, int m0, int k0, int lid, uint32_t a[4]) {
    uint32_t addr = (uint32_t)__cvta_generic_to_shared(
        P + (size_t)(m0 + (lid & 15)) * strideH + k0 + ((lid >> 4) << 3));
    asm volatile("ldmatrix.sync.aligned.m8n8.x4.shared.b16 {%0,%1,%2,%3}, [%4];"
        : "=r"(a[0]), "=r"(a[1]), "=r"(a[2]), "=r"(a[3]) : "r"(addr));
}

// ---------------- weight prep: pre-split hi/lo half planes ----------------
__global__ void prep_kernel(const float* __restrict__ nn1W, const float* __restrict__ nn1b,
                            const float* __restrict__ nn2W, const float* __restrict__ W2,
                            const float* __restrict__ W1, const float* __restrict__ wih0)
{
    int idx = blockIdx.x * 256 + threadIdx.x;   // 96 blocks -> 24576
    __half h, l;
    if (idx < 64 * 16) {
        int n = idx >> 4, k = idx & 15;
        float v = (k < 10) ? W1[k * 64 + n] : 0.f;
        splith(v, h, l); g_w1h[idx] = h; g_w1l[idx] = l;
    }
    if (idx < 128 * 64) {
        int n = idx >> 6, k = idx & 63;
        splith(W2[k * 128 + n], h, l); g_w2Th[idx] = h; g_w2Tl[idx] = l;
    }
    if (idx < 96 * 256) {
        int n = idx >> 8, k = idx & 255;
        float v = 0.f;
        if (n < 94) {
            if (k < 128) v = nn1W[k * 94 + n];
            else { int kk = k - 128; v = 0.25f * nn1W[(128 + kk) * 94 + n] + nn1W[(256 + kk) * 94 + n]; }
        }
        splith(v, h, l); g_nn1Th[idx] = h; g_nn1Tl[idx] = l;
    }
    if (idx < 64 * 96) {
        int n = idx / 96, k = idx % 96;
        float v = (k < 94) ? nn2W[k * 64 + n] : 0.f;
        splith(v, h, l); g_nn2Th[idx] = h; g_nn2Tl[idx] = l;
    }
    if (idx < 96) g_nn1bp[idx] = (idx < 94) ? nn1b[idx] : 0.f;
    if (idx < 96 * 256) { int gg = idx >> 8, d = idx & 255; g_wih0T[d * 96 + gg] = wih0[idx]; }
}

// ================= EC kernel: KNN + EdgeConv, register-chained l1->l2 =================
#define EC_XS    0        // 2560
#define EC_NBR   2560     // 2048
#define EC_W1H   4608     // [64][24] half = 3072
#define EC_W1L   7680     // 3072
#define EC_B1    10752    // 256
#define EC_B2    11008    // 512
#define EC_W2H   11520    // [128][72] half = 18432
#define EC_W2L   29952    // 18432
#define EC_SMEM  48384

__global__ void __launch_bounds__(256, 2) ec_kernel(
    const float* __restrict__ x, const float* __restrict__ b1, const float* __restrict__ b2)
{
    extern __shared__ __align__(16) char smem[];
    float* xs   = (float*)(smem + EC_XS);
    int*   nbr  = (int*)(smem + EC_NBR);
    __half* W1H = (__half*)(smem + EC_W1H);
    __half* W1L = (__half*)(smem + EC_W1L);
    float* b1s  = (float*)(smem + EC_B1);
    float* b2s  = (float*)(smem + EC_B2);
    __half* W2H = (__half*)(smem + EC_W2H);
    __half* W2L = (__half*)(smem + EC_W2L);

    const int tid = threadIdx.x, wid = tid >> 5, lid = tid & 31;
    const int qr = lid >> 2, qc = lid & 3;
    const int g = blockIdx.x;
    const size_t base = (size_t)g * NP;

    for (int i = tid; i < NP * 5; i += 256) xs[i] = x[base * 5 + i];
    for (int i = tid; i < 512; i += 256) {
        int n = i >> 3, kw = i & 7;
        ((uint32_t*)W1H)[n * 12 + kw] = ((const uint32_t*)g_w1h)[i];
        ((uint32_t*)W1L)[n * 12 + kw] = ((const uint32_t*)g_w1l)[i];
    }
    if (tid < 64) b1s[tid] = b1[tid];
    if (tid >= 64 && tid < 192) b2s[tid - 64] = b2[tid - 64];
    for (int i = tid; i < 4096; i += 256) {
        int n = i >> 5, kw = i & 31;
        ((uint32_t*)W2H)[n * 36 + kw] = ((const uint32_t*)g_w2Th)[i];
        ((uint32_t*)W2L)[n * 36 + kw] = ((const uint32_t*)g_w2Tl)[i];
    }
    __syncthreads();

    // ---- KNN (thread = node), branchless, stable ties
    if (tid < NP) {
        const float px = xs[tid * 5 + 0], py = xs[tid * 5 + 1], pz = xs[tid * 5 + 2];
        float d0 = 1e30f, d1 = 1e30f, d2v = 1e30f, d3 = 1e30f;
        int i0 = 0, i1 = 0, i2 = 0, i3 = 0;
#pragma unroll 4
        for (int j = 0; j < NP; j++) {
            float dx = xs[j * 5 + 0] - px, dy = xs[j * 5 + 1] - py, dz = xs[j * 5 + 2] - pz;
            float dd = dx * dx + dy * dy + dz * dz;
            dd = (j == tid) ? 1e30f : dd;
            bool c0 = dd < d0, c1 = dd < d1, c2 = dd < d2v, c3 = dd < d3;
            i3 = c2 ? i2 : (c3 ? j : i3);  d3  = c2 ? d2v : (c3 ? dd : d3);
            i2 = c1 ? i1 : (c2 ? j : i2);  d2v = c1 ? d1  : (c2 ? dd : d2v);
            i1 = c0 ? i0 : (c1 ? j : i1);  d1  = c0 ? d0  : (c1 ? dd : d1);
            i0 = c0 ? j : i0;              d0  = c0 ? dd  : d0;
        }
        nbr[tid * 4 + 0] = i0; nbr[tid * 4 + 1] = i1; nbr[tid * 4 + 2] = i2; nbr[tid * 4 + 3] = i3;
    }
    __syncthreads();

    // ---- main loop: warp-independent 16-edge tiles, NO block syncs
    for (int it = 0; it < 4; it++) {
        const int tile = it * 8 + wid;
        const int node = tile * 4 + (qr & 3);
        const int kb = (qr >> 2) & 1;
        const int j0 = nbr[node * 4 + kb];
        const int j1 = nbr[node * 4 + kb + 2];

        // edge features in registers -> l1 A-frag (split x3 for layer-1)
        uint32_t a1h[4], a1l[4];
        {
            const int d0 = 2 * qc, d2 = 8 + 2 * qc;
            float f0, f1, f2, f3, f4, f5, f6, f7;
            if (d0 < 5) { f0 = xs[node * 5 + d0]; f2 = f0; }
            else        { f0 = xs[j0 * 5 + d0 - 5] - xs[node * 5 + d0 - 5];
                          f2 = xs[j1 * 5 + d0 - 5] - xs[node * 5 + d0 - 5]; }
            if (d0 + 1 < 5) { f1 = xs[node * 5 + d0 + 1]; f3 = f1; }
            else            { f1 = xs[j0 * 5 + d0 - 4] - xs[node * 5 + d0 - 4];
                              f3 = xs[j1 * 5 + d0 - 4] - xs[node * 5 + d0 - 4]; }
            if (d2 < 10) {
                f4 = xs[j0 * 5 + 3] - xs[node * 5 + 3];
                f5 = xs[j0 * 5 + 4] - xs[node * 5 + 4];
                f6 = xs[j1 * 5 + 3] - xs[node * 5 + 3];
                f7 = xs[j1 * 5 + 4] - xs[node * 5 + 4];
            } else { f4 = 0.f; f5 = 0.f; f6 = 0.f; f7 = 0.f; }
            splitpack(f0, f1, a1h[0], a1l[0]);
            splitpack(f2, f3, a1h[1], a1l[1]);
            splitpack(f4, f5, a1h[2], a1l[2]);
            splitpack(f6, f7, a1h[3], a1l[3]);
        }

        // layer-1: 8 nt (64 cols), K=16, x3
        float acc1[8][4];
#pragma unroll
        for (int j = 0; j < 8; j++) { acc1[j][0]=0.f; acc1[j][1]=0.f; acc1[j][2]=0.f; acc1[j][3]=0.f; }
#pragma unroll
        for (int jp = 0; jp < 4; jp++) {
            uint32_t bh4[4], bl4[4];
            ldsm4(W1H, 24, jp * 16, 0, lid, bh4);
            ldsm4(W1L, 24, jp * 16, 0, lid, bl4);
            uint32_t b0h[2] = {bh4[0], bh4[2]}, b1h[2] = {bh4[1], bh4[3]};
            uint32_t b0l[2] = {bl4[0], bl4[2]}, b1l[2] = {bl4[1], bl4[3]};
            mma3h(acc1[jp * 2],     a1h, a1l, b0h, b0l);
            mma3h(acc1[jp * 2 + 1], a1h, a1l, b1h, b1l);
        }

        // layer-2: A plain fp16 from acc1 (bias+relu in regs), 16 nt, K=64, x2
        float acc2[16][4];
#pragma unroll
        for (int j = 0; j < 16; j++) { acc2[j][0]=0.f; acc2[j][1]=0.f; acc2[j][2]=0.f; acc2[j][3]=0.f; }
#pragma unroll
        for (int ks = 0; ks < 4; ks++) {
            uint32_t a2[4];
            {
                const int c0 = (2 * ks) * 8 + 2 * qc;
                const int c2 = (2 * ks + 1) * 8 + 2 * qc;
                float v0 = fmaxf(acc1[2 * ks][0] + b1s[c0], 0.f);
                float v1 = fmaxf(acc1[2 * ks][1] + b1s[c0 + 1], 0.f);
                float v2 = fmaxf(acc1[2 * ks][2] + b1s[c0], 0.f);
                float v3 = fmaxf(acc1[2 * ks][3] + b1s[c0 + 1], 0.f);
                float v4 = fmaxf(acc1[2 * ks + 1][0] + b1s[c2], 0.f);
                float v5 = fmaxf(acc1[2 * ks + 1][1] + b1s[c2 + 1], 0.f);
                float v6 = fmaxf(acc1[2 * ks + 1][2] + b1s[c2], 0.f);
                float v7 = fmaxf(acc1[2 * ks + 1][3] + b1s[c2 + 1], 0.f);
                a2[0] = packf(v0, v1); a2[1] = packf(v2, v3);
                a2[2] = packf(v4, v5); a2[3] = packf(v6, v7);
            }
#pragma unroll
            for (int jp = 0; jp < 8; jp++) {
                uint32_t bh4[4], bl4[4];
                ldsm4(W2H, 72, jp * 16, ks * 16, lid, bh4);
                ldsm4(W2L, 72, jp * 16, ks * 16, lid, bl4);
                uint32_t b0h[2] = {bh4[0], bh4[2]}, b1h[2] = {bh4[1], bh4[3]};
                uint32_t b0l[2] = {bl4[0], bl4[2]}, b1l[2] = {bl4[1], bl4[3]};
                mma2h(acc2[jp * 2],     a2, b0h, b0l);
                mma2h(acc2[jp * 2 + 1], a2, b1h, b1l);
            }
        }

        // epilogue: +b2, relu; in-thread k={kb,kb+2}; XOR-16 pairs kb<->kb^1; fp16 store
        {
            uint32_t* Gh = (uint32_t*)g_hagg + (base + node) * 128;
#pragma unroll
            for (int j = 0; j < 16; j++) {
                const int col = j * 8 + 2 * qc;
                float v0 = fmaxf(acc2[j][0] + b2s[col], 0.f);
                float v1 = fmaxf(acc2[j][1] + b2s[col + 1], 0.f);
                float v2 = fmaxf(acc2[j][2] + b2s[col], 0.f);
                float v3 = fmaxf(acc2[j][3] + b2s[col + 1], 0.f);
                float mx0 = fmaxf(v0, v2), mx1 = fmaxf(v1, v3);
                float sm0 = v0 + v2,       sm1 = v1 + v3;
                mx0 = fmaxf(mx0, __shfl_xor_sync(0xffffffffu, mx0, 16));
                mx1 = fmaxf(mx1, __shfl_xor_sync(0xffffffffu, mx1, 16));
                sm0 += __shfl_xor_sync(0xffffffffu, sm0, 16);
                sm1 += __shfl_xor_sync(0xffffffffu, sm1, 16);
                if ((qr < 4) == (j < 8)) {
                    Gh[col >> 1]        = packf(mx0, mx1);
                    Gh[64 + (col >> 1)] = packf(sm0, sm1);
                }
            }
        }
    }
}

// ================= NN kernel: nn1(x2) + nn2(x2) + segreduce -> g_xin =================
#define NN_ASH  0         // A chunk [128][40] half = 10240
#define NN_B1H  10240     // [96][40] half = 7680
#define NN_B1L  17920     // 7680 -> end 25600
#define NN_B2H  0         // overlay after nn1: [64][104] half = 13312
#define NN_B2L  13312     // 13312 -> end 26624
#define NN_H2H  26624     // [128][104] half = 26624 (h2 fp32 [128][68] overlays after nn2)
#define NN_RED  61440     // 3072
#define NN_B1V  64512     // 384
#define NN_B2V  64896     // 256
#define NN_SMEM 65152

__global__ void __launch_bounds__(256, 2) nn_kernel(const float* __restrict__ nn2b)
{
    extern __shared__ __align__(16) char smem[];
    __half* AsH = (__half*)(smem + NN_ASH);
    __half* B1H = (__half*)(smem + NN_B1H);
    __half* B1L = (__half*)(smem + NN_B1L);
    __half* B2H = (__half*)(smem + NN_B2H);
    __half* B2L = (__half*)(smem + NN_B2L);
    __half* H2H = (__half*)(smem + NN_H2H);
    float* red  = (float*)(smem + NN_RED);
    float* b1v  = (float*)(smem + NN_B1V);
    float* b2v  = (float*)(smem + NN_B2V);

    const int tid = threadIdx.x, wid = tid >> 5, lid = tid & 31;
    const int rw = wid >> 1, nh = wid & 1;
    const int qr = lid >> 2, qc = lid & 3;
    const int g = blockIdx.x;
    const __half* Ah = g_hagg + (size_t)g * NP * 256;

    if (tid < 96) b1v[tid] = g_nn1bp[tid];
    if (tid >= 96 && tid < 160) b2v[tid - 96] = nn2b[tid - 96];

    // ---- nn1: [128][256] @ [256][96]; A plain fp16, x2
    float acc1[2][6][4];
#pragma unroll
    for (int rt = 0; rt < 2; rt++)
#pragma unroll
        for (int j = 0; j < 6; j++) { acc1[rt][j][0]=0.f; acc1[rt][j][1]=0.f; acc1[rt][j][2]=0.f; acc1[rt][j][3]=0.f; }
    for (int kc = 0; kc < 8; kc++) {
        for (int i = tid; i < 512; i += 256) {
            int r = i >> 2, q = i & 3;
            *(uint4*)(AsH + r * 40 + q * 8) = *(const uint4*)(Ah + r * 256 + kc * 32 + q * 8);
        }
        for (int i = tid; i < 1536; i += 256) {
            int n = i >> 4, kw = i & 15;
            ((uint32_t*)B1H)[n * 20 + kw] = ((const uint32_t*)g_nn1Th)[n * 128 + kc * 16 + kw];
            ((uint32_t*)B1L)[n * 20 + kw] = ((const uint32_t*)g_nn1Tl)[n * 128 + kc * 16 + kw];
        }
        __syncthreads();
#pragma unroll
        for (int ks = 0; ks < 2; ks++) {
            uint32_t ah[2][4];
            ldsm4(AsH, 40, rw * 32,      ks * 16, lid, ah[0]);
            ldsm4(AsH, 40, rw * 32 + 16, ks * 16, lid, ah[1]);
#pragma unroll
            for (int jp = 0; jp < 3; jp++) {
                uint32_t bh4[4], bl4[4];
                ldsm4(B1H, 40, (nh * 6 + jp * 2) * 8, ks * 16, lid, bh4);
                ldsm4(B1L, 40, (nh * 6 + jp * 2) * 8, ks * 16, lid, bl4);
                uint32_t b0h[2] = {bh4[0], bh4[2]}, b1h[2] = {bh4[1], bh4[3]};
                uint32_t b0l[2] = {bl4[0], bl4[2]}, b1l[2] = {bl4[1], bl4[3]};
                mma2h(acc1[0][jp * 2],     ah[0], b0h, b0l);
                mma2h(acc1[1][jp * 2],     ah[1], b0h, b0l);
                mma2h(acc1[0][jp * 2 + 1], ah[0], b1h, b1l);
                mma2h(acc1[1][jp * 2 + 1], ah[1], b1h, b1l);
            }
        }
        __syncthreads();
    }
    // epilogue1: H2 plain fp16 = relu(acc1 + b1v); stage B2 planes (overlay A/B1)
    {
#pragma unroll
        for (int rt = 0; rt < 2; rt++) {
            int r0 = rw * 32 + rt * 16 + qr, r1 = r0 + 8;
#pragma unroll
            for (int j = 0; j < 6; j++) {
                int col = (nh * 6 + j) * 8 + 2 * qc;
                float v0 = fmaxf(acc1[rt][j][0] + b1v[col], 0.f), v1 = fmaxf(acc1[rt][j][1] + b1v[col + 1], 0.f);
                float v2 = fmaxf(acc1[rt][j][2] + b1v[col], 0.f), v3 = fmaxf(acc1[rt][j][3] + b1v[col + 1], 0.f);
                ((uint32_t*)H2H)[r0 * 52 + (col >> 1)] = packf(v0, v1);
                ((uint32_t*)H2H)[r1 * 52 + (col >> 1)] = packf(v2, v3);
            }
        }
        for (int i = tid; i < 3072; i += 256) {
            int n = i / 48, kw = i % 48;
            ((uint32_t*)B2H)[n * 52 + kw] = ((const uint32_t*)g_nn2Th)[n * 48 + kw];
            ((uint32_t*)B2L)[n * 52 + kw] = ((const uint32_t*)g_nn2Tl)[n * 48 + kw];
        }
    }
    __syncthreads();

    // ---- nn2: [128][96] @ [96][64], K=96, x2 (A plain fp16)
    float acc2[2][4][4];
#pragma unroll
    for (int rt = 0; rt < 2; rt++)
#pragma unroll
        for (int j = 0; j < 4; j++) { acc2[rt][j][0]=0.f; acc2[rt][j][1]=0.f; acc2[rt][j][2]=0.f; acc2[rt][j][3]=0.f; }
#pragma unroll
    for (int ks = 0; ks < 6; ks++) {
        uint32_t ah[2][4];
        ldsm4(H2H, 104, rw * 32,      ks * 16, lid, ah[0]);
        ldsm4(H2H, 104, rw * 32 + 16, ks * 16, lid, ah[1]);
#pragma unroll
        for (int jp = 0; jp < 2; jp++) {
            uint32_t bh4[4], bl4[4];
            ldsm4(B2H, 104, (nh * 4 + jp * 2) * 8, ks * 16, lid, bh4);
            ldsm4(B2L, 104, (nh * 4 + jp * 2) * 8, ks * 16, lid, bl4);
            uint32_t b0h[2] = {bh4[0], bh4[2]}, b1h[2] = {bh4[1], bh4[3]};
            uint32_t b0l[2] = {bl4[0], bl4[2]}, b1l[2] = {bl4[1], bl4[3]};
            mma2h(acc2[0][jp * 2],     ah[0], b0h, b0l);
            mma2h(acc2[1][jp * 2],     ah[1], b0h, b0l);
            mma2h(acc2[0][jp * 2 + 1], ah[0], b1h, b1l);
            mma2h(acc2[1][jp * 2 + 1], ah[1], b1h, b1l);
        }
    }
    __syncthreads();
    float* h2 = (float*)(smem + NN_H2H);          // [128][68] fp32 overlay
    {
#pragma unroll
        for (int rt = 0; rt < 2; rt++) {
            int r0 = rw * 32 + rt * 16 + qr, r1 = r0 + 8;
#pragma unroll
            for (int j = 0; j < 4; j++) {
                int col = (nh * 4 + j) * 8 + 2 * qc;
                float2 u0 = { acc2[rt][j][0] + b2v[col], acc2[rt][j][1] + b2v[col + 1] };
                float2 u1 = { acc2[rt][j][2] + b2v[col], acc2[rt][j][3] + b2v[col + 1] };
                *(float2*)&h2[r0 * 68 + col] = u0;
                *(float2*)&h2[r1 * 68 + col] = u1;
            }
        }
    }
    __syncthreads();

    // ---- segment max/min/sum/mean + relu -> g_xin (permute fused)
    {
        int c = tid & 63, q = tid >> 6;
        float mx = -1e30f, mn = 1e30f, sm = 0.f;
        for (int r = q * 32; r < q * 32 + 32; r++) {
            float v = h2[r * 68 + c];
            mx = fmaxf(mx, v); mn = fminf(mn, v); sm += v;
        }
        red[q * 192 + c] = mx; red[q * 192 + 64 + c] = mn; red[q * 192 + 128 + c] = sm;
        __syncthreads();
        if (tid < 64) {
            float MX = red[c], MN = red[64 + c], SM = red[128 + c];
            for (int qq = 1; qq < 4; qq++) {
                MX = fmaxf(MX, red[qq * 192 + c]);
                MN = fminf(MN, red[qq * 192 + 64 + c]);
                SM += red[qq * 192 + 128 + c];
            }
            const int t = g >> 10, qg = g & 1023;
            const int i = qg >> 2;
            float* xrow = g_xin + ((size_t)((t << 10) + (qg & 3) * 256) << 8) + i;
            xrow[(size_t)c * 256]         = fmaxf(MX, 0.f);
            xrow[(size_t)(64 + c) * 256]  = fmaxf(MN, 0.f);
            xrow[(size_t)(128 + c) * 256] = fmaxf(SM, 0.f);
            xrow[(size_t)(192 + c) * 256] = fmaxf(SM * (1.f / 128.f), 0.f);
        }
    }
}

// ---------------- GI = xin @ wih0T + bih0; coalesced A, 8-row tiles, grid 256 ----------------
__global__ void __launch_bounds__(256) gi_gemm_kernel(
    const float* __restrict__ W, const float* __restrict__ bias, float* __restrict__ C)
{
    __shared__ float As[8][260];
    __shared__ float Ws[32][96];
    const int tid = threadIdx.x;
    const int bm = blockIdx.x * 8;
    const int r = tid >> 5, c = tid & 31;

    {
        const float* arow = g_xin + (size_t)(bm + r) * 256;
        for (int k = c; k < 256; k += 32) As[r][k] = arow[k];
    }
    float a0 = 0.f, a1 = 0.f, a2 = 0.f;
    for (int kc = 0; kc < 8; kc++) {
        for (int i = tid; i < 3072; i += 256)
            (&Ws[0][0])[i] = W[kc * 3072 + i];
        __syncthreads();
#pragma unroll
        for (int k = 0; k < 32; k++) {
            const float av = As[r][kc * 32 + k];
            a0 = fmaf(av, Ws[k][c], a0);
            a1 = fmaf(av, Ws[k][c + 32], a1);
            a2 = fmaf(av, Ws[k][c + 64], a2);
        }
        __syncthreads();
    }
    float* o = C + (size_t)(bm + r) * 96;
    o[c] = a0 + bias[c];
    o[c + 32] = a1 + bias[c + 32];
    o[c + 64] = a2 + bias[c + 64];
}

// ---------------- fused GRU: both layers x both timesteps; warp = row ----------------
__global__ void __launch_bounds__(512) gru_all_kernel(
    const float* __restrict__ gi,     // [2][1024][96]
    const float* __restrict__ h1in,   // [2][1024][32]
    const float* __restrict__ wih1, const float* __restrict__ bih1,
    const float* __restrict__ whh0, const float* __restrict__ bhh0,
    const float* __restrict__ whh1, const float* __restrict__ bhh1)
{
    __shared__ float w0[96][33], w1[96][33], wi1[96][33];
    const int tid = threadIdx.x;
    const int wr = tid >> 5, u = tid & 31;
    const int row = blockIdx.x * 16 + wr;

    for (int i = tid; i < 3072; i += 512) {
        w0[i >> 5][i & 31] = whh0[i];
        w1[i >> 5][i & 31] = whh1[i];
        wi1[i >> 5][i & 31] = wih1[i];
    }
    __syncthreads();

    float h0 = h1in[row * 32 + u];
    float hv1 = h1in[32768 + row * 32 + u];
    const float b0r = bhh0[u], b0z = bhh0[32 + u], b0n = bhh0[64 + u];
    const float bi1r = bih1[u], bi1z = bih1[32 + u], bi1n = bih1[64 + u];
    const float b1r = bhh1[u], b1z = bhh1[32 + u], b1n = bhh1[64 + u];

#pragma unroll
    for (int t = 0; t < 2; t++) {
        const float* gr0 = gi + t * 98304 + (size_t)row * 96;
        float gr = gr0[u], gz = gr0[32 + u], gn = gr0[64 + u];
        float hr = b0r, hz = b0z, hn = b0n;
#pragma unroll
        for (int d = 0; d < 32; d++) {
            float hv = __shfl_sync(0xffffffffu, h0, d);
            hr = fmaf(hv, w0[u][d], hr);
            hz = fmaf(hv, w0[32 + u][d], hz);
            hn = fmaf(hv, w0[64 + u][d], hn);
        }
        float rr = 1.f / (1.f + expf(-(gr + hr)));
        float zz = 1.f / (1.f + expf(-(gz + hz)));
        float nn = tanhf(gn + rr * hn);
        h0 = (1.f - zz) * nn + zz * h0;

        float xr = bi1r, xz = bi1z, xn = bi1n;
        float yr = b1r, yz = b1z, yn = b1n;
#pragma unroll
        for (int d = 0; d < 32; d++) {
            float xv = __shfl_sync(0xffffffffu, h0, d);
            xr = fmaf(xv, wi1[u][d], xr);
            xz = fmaf(xv, wi1[32 + u][d], xz);
            xn = fmaf(xv, wi1[64 + u][d], xn);
            float hv = __shfl_sync(0xffffffffu, hv1, d);
            yr = fmaf(hv, w1[u][d], yr);
            yz = fmaf(hv, w1[32 + u][d], yz);
            yn = fmaf(hv, w1[64 + u][d], yn);
        }
        float r1 = 1.f / (1.f + expf(-(xr + yr)));
        float z1 = 1.f / (1.f + expf(-(xz + yz)));
        float n1 = tanhf(xn + r1 * yn);
        hv1 = (1.f - z1) * n1 + z1 * hv1;
        g_out1[t * 32768 + row * 32 + u] = hv1;
    }
    g_out0[32768 + row * 32 + u] = h0;   // hT of layer 0
}

// ---------------- final head + hT pack ----------------
__global__ void final_kernel(const float* __restrict__ nn4W, const float* __restrict__ nn4b,
                             float* __restrict__ out, int out_size)
{
    const int idx = blockIdx.x * 256 + threadIdx.x;
    if (idx >= out_size) return;
    if (idx < 2048) {
        const int t  = idx >> 10;
        const int ch = (idx >> 5) & 31;
        const int b0 = (idx & 31) * 32;
        float acc = nn4b[0];
#pragma unroll
        for (int c = 0; c < 32; c++) {
            const float v = g_out1[t * 32768 + (b0 + c) * 32 + ch];
            acc = fmaf(fmaxf(v, 0.f), nn4W[c], acc);
        }
        out[idx] = fmaxf(acc, 0.f);
    } else if (idx < 2048 + 65536) {
        const int j = idx - 2048;
        out[idx] = (j < 32768) ? g_out0[32768 + j] : g_out1[32768 + (j - 32768)];
    }
}

// ---------------- launch ----------------
extern "C" void kernel_launch(void* const* d_in, const int* in_sizes, int n_in,
                              void* d_out, int out_size)
{
    const float* x    = (const float*)d_in[0];
    const float* h1   = (const float*)d_in[2];
    const float* W1   = (const float*)d_in[3];
    const float* b1   = (const float*)d_in[4];
    const float* W2   = (const float*)d_in[5];
    const float* b2   = (const float*)d_in[6];
    const float* nn1W = (const float*)d_in[7];
    const float* nn1b = (const float*)d_in[8];
    const float* nn2W = (const float*)d_in[9];
    const float* nn2b = (const float*)d_in[10];
    const float* nn4W = (const float*)d_in[11];
    const float* nn4b = (const float*)d_in[12];
    const float* wih0 = (const float*)d_in[13];
    const float* whh0 = (const float*)d_in[14];
    const float* bih0 = (const float*)d_in[15];
    const float* bhh0 = (const float*)d_in[16];
    const float* wih1 = (const float*)d_in[17];
    const float* whh1 = (const float*)d_in[18];
    const float* bih1 = (const float*)d_in[19];
    const float* bhh1 = (const float*)d_in[20];
    float* out = (float*)d_out;

    float *gi, *wih0T;
    cudaGetSymbolAddress((void**)&gi,    g_gi);
    cudaGetSymbolAddress((void**)&wih0T, g_wih0T);

    cudaFuncSetAttribute(ec_kernel, cudaFuncAttributeMaxDynamicSharedMemorySize, EC_SMEM);
    cudaFuncSetAttribute(nn_kernel, cudaFuncAttributeMaxDynamicSharedMemorySize, NN_SMEM);

    prep_kernel<<<96, 256>>>(nn1W, nn1b, nn2W, W2, W1, wih0);
    ec_kernel<<<NG, 256, EC_SMEM>>>(x, b1, b2);
    nn_kernel<<<NG, 256, NN_SMEM>>>(nn2b);
    gi_gemm_kernel<<<256, 256>>>(wih0T, bih0, gi);
    gru_all_kernel<<<64, 512>>>(gi, h1, wih1, bih1, whh0, bhh0, whh1, bhh1);
    final_kernel<<<(out_size + 255) / 256, 256>>>(nn4W, nn4b, out, out_size);
}

// round 16
// speedup vs baseline: 1.6808x; 1.1631x over previous
#include <cuda_runtime.h>
#include <cuda_fp16.h>
#include <math.h>
#include <stdint.h>

#define NG 2048
#define NP 128

// ---------------- scratch (device globals) ----------------
__device__ float g_xin[2 * 1024 * 256];
__device__ float g_gi[2 * 1024 * 96];
__device__ float g_out0[2 * 1024 * 32];
__device__ float g_out1[2 * 1024 * 32];
__device__ __half g_w1h[64 * 16],   g_w1l[64 * 16];     // W1^T padded k16, [64][16]
__device__ __half g_w2Th[128 * 64], g_w2Tl[128 * 64];   // edge W2^T
__device__ __half g_nn1Th[96 * 256], g_nn1Tl[96 * 256]; // folded nn1^T
__device__ __half g_nn2Th[64 * 96],  g_nn2Tl[64 * 96];  // nn2^T padded
__device__ float g_nn1bp[96];
__device__ float g_wih0T[256 * 96];

// ---------------- helpers ----------------
__device__ __forceinline__ void splith(float x, __half& h, __half& l) {
    h = __float2half_rn(x);
    l = __float2half_rn(x - __half2float(h));
}
__device__ __forceinline__ uint32_t packh(__half a, __half b) {
    __half2 p = __halves2half2(a, b);
    return *(uint32_t*)&p;
}
__device__ __forceinline__ void splitpack(float x0, float x1, uint32_t& hi, uint32_t& lo) {
    __half h0, l0, h1, l1;
    splith(x0, h0, l0); splith(x1, h1, l1);
    hi = packh(h0, h1); lo = packh(l0, l1);
}
__device__ __forceinline__ uint32_t packf(float x0, float x1) {
    return packh(__float2half_rn(x0), __float2half_rn(x1));
}
__device__ __forceinline__ void mma16(float d[4], const uint32_t a[4], const uint32_t b[2]) {
    asm volatile(
        "mma.sync.aligned.m16n8k16.row.col.f32.f16.f16.f32 "
        "{%0,%1,%2,%3},{%4,%5,%6,%7},{%8,%9},{%0,%1,%2,%3};"
        : "+f"(d[0]), "+f"(d[1]), "+f"(d[2]), "+f"(d[3])
        : "r"(a[0]), "r"(a[1]), "r"(a[2]), "r"(a[3]), "r"(b[0]), "r"(b[1]));
}
__device__ __forceinline__ void mma3h(float d[4], const uint32_t ah[4], const uint32_t al[4],
                                      const uint32_t bh[2], const uint32_t bl[2]) {
    mma16(d, ah, bh); mma16(d, ah, bl); mma16(d, al, bh);
}
__device__ __forceinline__ void mma2h(float d[4], const uint32_t ah[4],
                                      const uint32_t bh[2], const uint32_t bl[2]) {
    mma16(d, ah, bh); mma16(d, ah, bl);
}
// ldmatrix x4 (A m16k16 frag, or B-pair load). stride in halves (8-mult).
__device__ __forceinline__ void ldsm4(const __half* P, int strideH, int m0, int k0, int lid, uint32_t a[4]) {
    uint32_t addr = (uint32_t)__cvta_generic_to_shared(
        P + (size_t)(m0 + (lid & 15)) * strideH + k0 + ((lid >> 4) << 3));
    asm volatile("ldmatrix.sync.aligned.m8n8.x4.shared.b16 {%0,%1,%2,%3}, [%4];"
        : "=r"(a[0]), "=r"(a[1]), "=r"(a[2]), "=r"(a[3]) : "r"(addr));
}

// ---------------- weight prep: pre-split hi/lo half planes ----------------
__global__ void prep_kernel(const float* __restrict__ nn1W, const float* __restrict__ nn1b,
                            const float* __restrict__ nn2W, const float* __restrict__ W2,
                            const float* __restrict__ W1, const float* __restrict__ wih0)
{
    int idx = blockIdx.x * 256 + threadIdx.x;   // 96 blocks -> 24576
    __half h, l;
    if (idx < 64 * 16) {
        int n = idx >> 4, k = idx & 15;
        float v = (k < 10) ? W1[k * 64 + n] : 0.f;
        splith(v, h, l); g_w1h[idx] = h; g_w1l[idx] = l;
    }
    if (idx < 128 * 64) {
        int n = idx >> 6, k = idx & 63;
        splith(W2[k * 128 + n], h, l); g_w2Th[idx] = h; g_w2Tl[idx] = l;
    }
    if (idx < 96 * 256) {
        int n = idx >> 8, k = idx & 255;
        float v = 0.f;
        if (n < 94) {
            if (k < 128) v = nn1W[k * 94 + n];
            else { int kk = k - 128; v = 0.25f * nn1W[(128 + kk) * 94 + n] + nn1W[(256 + kk) * 94 + n]; }
        }
        splith(v, h, l); g_nn1Th[idx] = h; g_nn1Tl[idx] = l;
    }
    if (idx < 64 * 96) {
        int n = idx / 96, k = idx % 96;
        float v = (k < 94) ? nn2W[k * 64 + n] : 0.f;
        splith(v, h, l); g_nn2Th[idx] = h; g_nn2Tl[idx] = l;
    }
    if (idx < 96) g_nn1bp[idx] = (idx < 94) ? nn1b[idx] : 0.f;
    if (idx < 96 * 256) { int gg = idx >> 8, d = idx & 255; g_wih0T[d * 96 + gg] = wih0[idx]; }
}

// ================= fused kernel: KNN + EdgeConv + nn1 + nn2 + segreduce -> g_xin =================
// EC-phase layout
#define F_XS    0        // 2560
#define F_NBR   2560     // 2048
#define F_W1H   4608     // [64][16] half = 2048
#define F_W1L   6656     // 2048
#define F_B1S   8704     // 256
#define F_B2S   8960     // 512
#define F_W2H   9472     // [128][72] half = 18432
#define F_W2L   27904    // 18432 -> 46336
#define F_HAGG  46336    // [128][264] half = 67584 -> 113920
#define F_SMEM  113920
// NN-phase overlays (region 0..46336 dead after EC; haggS dead after nn1)
#define N_H2H   0        // [128][104] half = 26624
#define N_B1H   26624    // [96][40] half = 7680
#define N_B1L   34304    // 7680 -> 41984
#define N_RED   41984    // 3072 -> 45056
#define N_B1V   45056    // 384
#define N_B2V   45440    // 256 -> 45696
#define N_B2H   46336    // [64][104] half = 13312 (overlay haggS after nn1)
#define N_B2L   59648    // 13312 -> 72960
#define N_H2F   46336    // h2 fp32 [128][68] = 34816 (overlay B2/haggS after nn2)

__global__ void __launch_bounds__(256, 2) fused_kernel(
    const float* __restrict__ x, const float* __restrict__ b1, const float* __restrict__ b2,
    const float* __restrict__ nn2b)
{
    extern __shared__ __align__(16) char smem[];
    float* xs    = (float*)(smem + F_XS);
    int*   nbr   = (int*)(smem + F_NBR);
    __half* W1H  = (__half*)(smem + F_W1H);
    __half* W1L  = (__half*)(smem + F_W1L);
    float* b1s   = (float*)(smem + F_B1S);
    float* b2s   = (float*)(smem + F_B2S);
    __half* W2H  = (__half*)(smem + F_W2H);
    __half* W2L  = (__half*)(smem + F_W2L);
    __half* HAG  = (__half*)(smem + F_HAGG);

    const int tid = threadIdx.x, wid = tid >> 5, lid = tid & 31;
    const int qr = lid >> 2, qc = lid & 3;
    const int g = blockIdx.x;
    const size_t base = (size_t)g * NP;

    for (int i = tid; i < NP * 5; i += 256) xs[i] = x[base * 5 + i];
    for (int i = tid; i < 512; i += 256) {
        ((uint32_t*)W1H)[i] = ((const uint32_t*)g_w1h)[i];
        ((uint32_t*)W1L)[i] = ((const uint32_t*)g_w1l)[i];
    }
    if (tid < 64) b1s[tid] = b1[tid];
    if (tid >= 64 && tid < 192) b2s[tid - 64] = b2[tid - 64];
    for (int i = tid; i < 4096; i += 256) {
        int n = i >> 5, kw = i & 31;
        ((uint32_t*)W2H)[n * 36 + kw] = ((const uint32_t*)g_w2Th)[i];
        ((uint32_t*)W2L)[n * 36 + kw] = ((const uint32_t*)g_w2Tl)[i];
    }
    __syncthreads();

    // ---- KNN (thread = node), branchless, stable ties
    if (tid < NP) {
        const float px = xs[tid * 5 + 0], py = xs[tid * 5 + 1], pz = xs[tid * 5 + 2];
        float d0 = 1e30f, d1 = 1e30f, d2v = 1e30f, d3 = 1e30f;
        int i0 = 0, i1 = 0, i2 = 0, i3 = 0;
#pragma unroll 4
        for (int j = 0; j < NP; j++) {
            float dx = xs[j * 5 + 0] - px, dy = xs[j * 5 + 1] - py, dz = xs[j * 5 + 2] - pz;
            float dd = dx * dx + dy * dy + dz * dz;
            dd = (j == tid) ? 1e30f : dd;
            bool c0 = dd < d0, c1 = dd < d1, c2 = dd < d2v, c3 = dd < d3;
            i3 = c2 ? i2 : (c3 ? j : i3);  d3  = c2 ? d2v : (c3 ? dd : d3);
            i2 = c1 ? i1 : (c2 ? j : i2);  d2v = c1 ? d1  : (c2 ? dd : d2v);
            i1 = c0 ? i0 : (c1 ? j : i1);  d1  = c0 ? d0  : (c1 ? dd : d1);
            i0 = c0 ? j : i0;              d0  = c0 ? dd  : d0;
        }
        nbr[tid * 4 + 0] = i0; nbr[tid * 4 + 1] = i1; nbr[tid * 4 + 2] = i2; nbr[tid * 4 + 3] = i3;
    }
    __syncthreads();

    // ================= EC phase: warp-independent 16-edge tiles =================
    for (int it = 0; it < 4; it++) {
        const int tile = it * 8 + wid;
        const int node = tile * 4 + (qr & 3);
        const int kb = (qr >> 2) & 1;
        const int j0 = nbr[node * 4 + kb];
        const int j1 = nbr[node * 4 + kb + 2];

        // edge features in registers -> l1 A-frag (split, x3 layer-1)
        uint32_t a1h[4], a1l[4];
        {
            const int d0 = 2 * qc, d2 = 8 + 2 * qc;
            float f0, f1, f2, f3, f4, f5, f6, f7;
            if (d0 < 5) { f0 = xs[node * 5 + d0]; f2 = f0; }
            else        { f0 = xs[j0 * 5 + d0 - 5] - xs[node * 5 + d0 - 5];
                          f2 = xs[j1 * 5 + d0 - 5] - xs[node * 5 + d0 - 5]; }
            if (d0 + 1 < 5) { f1 = xs[node * 5 + d0 + 1]; f3 = f1; }
            else            { f1 = xs[j0 * 5 + d0 - 4] - xs[node * 5 + d0 - 4];
                              f3 = xs[j1 * 5 + d0 - 4] - xs[node * 5 + d0 - 4]; }
            if (d2 < 10) {
                f4 = xs[j0 * 5 + 3] - xs[node * 5 + 3];
                f5 = xs[j0 * 5 + 4] - xs[node * 5 + 4];
                f6 = xs[j1 * 5 + 3] - xs[node * 5 + 3];
                f7 = xs[j1 * 5 + 4] - xs[node * 5 + 4];
            } else { f4 = 0.f; f5 = 0.f; f6 = 0.f; f7 = 0.f; }
            splitpack(f0, f1, a1h[0], a1l[0]);
            splitpack(f2, f3, a1h[1], a1l[1]);
            splitpack(f4, f5, a1h[2], a1l[2]);
            splitpack(f6, f7, a1h[3], a1l[3]);
        }

        // layer-1: 8 nt, K=16, x3
        float acc1[8][4];
#pragma unroll
        for (int j = 0; j < 8; j++) { acc1[j][0]=0.f; acc1[j][1]=0.f; acc1[j][2]=0.f; acc1[j][3]=0.f; }
#pragma unroll
        for (int jp = 0; jp < 4; jp++) {
            uint32_t bh4[4], bl4[4];
            ldsm4(W1H, 16, jp * 16, 0, lid, bh4);
            ldsm4(W1L, 16, jp * 16, 0, lid, bl4);
            uint32_t b0h[2] = {bh4[0], bh4[2]}, b1h[2] = {bh4[1], bh4[3]};
            uint32_t b0l[2] = {bl4[0], bl4[2]}, b1l[2] = {bl4[1], bl4[3]};
            mma3h(acc1[jp * 2],     a1h, a1l, b0h, b0l);
            mma3h(acc1[jp * 2 + 1], a1h, a1l, b1h, b1l);
        }

        // layer-2: A plain fp16 from acc1, 16 nt, K=64, x2
        float acc2[16][4];
#pragma unroll
        for (int j = 0; j < 16; j++) { acc2[j][0]=0.f; acc2[j][1]=0.f; acc2[j][2]=0.f; acc2[j][3]=0.f; }
#pragma unroll
        for (int ks = 0; ks < 4; ks++) {
            uint32_t a2[4];
            {
                const int c0 = (2 * ks) * 8 + 2 * qc;
                const int c2 = (2 * ks + 1) * 8 + 2 * qc;
                float v0 = fmaxf(acc1[2 * ks][0] + b1s[c0], 0.f);
                float v1 = fmaxf(acc1[2 * ks][1] + b1s[c0 + 1], 0.f);
                float v2 = fmaxf(acc1[2 * ks][2] + b1s[c0], 0.f);
                float v3 = fmaxf(acc1[2 * ks][3] + b1s[c0 + 1], 0.f);
                float v4 = fmaxf(acc1[2 * ks + 1][0] + b1s[c2], 0.f);
                float v5 = fmaxf(acc1[2 * ks + 1][1] + b1s[c2 + 1], 0.f);
                float v6 = fmaxf(acc1[2 * ks + 1][2] + b1s[c2], 0.f);
                float v7 = fmaxf(acc1[2 * ks + 1][3] + b1s[c2 + 1], 0.f);
                a2[0] = packf(v0, v1); a2[1] = packf(v2, v3);
                a2[2] = packf(v4, v5); a2[3] = packf(v6, v7);
            }
#pragma unroll
            for (int jp = 0; jp < 8; jp++) {
                uint32_t bh4[4], bl4[4];
                ldsm4(W2H, 72, jp * 16, ks * 16, lid, bh4);
                ldsm4(W2L, 72, jp * 16, ks * 16, lid, bl4);
                uint32_t b0h[2] = {bh4[0], bh4[2]}, b1h[2] = {bh4[1], bh4[3]};
                uint32_t b0l[2] = {bl4[0], bl4[2]}, b1l[2] = {bl4[1], bl4[3]};
                mma2h(acc2[jp * 2],     a2, b0h, b0l);
                mma2h(acc2[jp * 2 + 1], a2, b1h, b1l);
            }
        }

        // epilogue: +b2, relu; in-thread k={kb,kb+2}; XOR-16 pairs; store into haggS smem
        {
            uint32_t* Gh = (uint32_t*)HAG + node * 132;   // 264 halves = 132 words
#pragma unroll
            for (int j = 0; j < 16; j++) {
                const int col = j * 8 + 2 * qc;
                float v0 = fmaxf(acc2[j][0] + b2s[col], 0.f);
                float v1 = fmaxf(acc2[j][1] + b2s[col + 1], 0.f);
                float v2 = fmaxf(acc2[j][2] + b2s[col], 0.f);
                float v3 = fmaxf(acc2[j][3] + b2s[col + 1], 0.f);
                float mx0 = fmaxf(v0, v2), mx1 = fmaxf(v1, v3);
                float sm0 = v0 + v2,       sm1 = v1 + v3;
                mx0 = fmaxf(mx0, __shfl_xor_sync(0xffffffffu, mx0, 16));
                mx1 = fmaxf(mx1, __shfl_xor_sync(0xffffffffu, mx1, 16));
                sm0 += __shfl_xor_sync(0xffffffffu, sm0, 16);
                sm1 += __shfl_xor_sync(0xffffffffu, sm1, 16);
                if ((qr < 4) == (j < 8)) {
                    Gh[col >> 1]        = packf(mx0, mx1);
                    Gh[64 + (col >> 1)] = packf(sm0, sm1);
                }
            }
        }
    }
    __syncthreads();   // EC done; haggS complete; EC-weight region now dead

    // ================= NN phase =================
    __half* B1H = (__half*)(smem + N_B1H);
    __half* B1L = (__half*)(smem + N_B1L);
    __half* B2H = (__half*)(smem + N_B2H);
    __half* B2L = (__half*)(smem + N_B2L);
    __half* H2H = (__half*)(smem + N_H2H);
    float* red  = (float*)(smem + N_RED);
    float* b1v  = (float*)(smem + N_B1V);
    float* b2v  = (float*)(smem + N_B2V);

    const int rw = wid >> 1, nh = wid & 1;

    if (tid < 96) b1v[tid] = g_nn1bp[tid];
    if (tid >= 96 && tid < 160) b2v[tid - 96] = nn2b[tid - 96];

    // ---- nn1: [128][256] @ [256][96]; A ldsm direct from haggS, x2
    float acc1[2][6][4];
#pragma unroll
    for (int rt = 0; rt < 2; rt++)
#pragma unroll
        for (int j = 0; j < 6; j++) { acc1[rt][j][0]=0.f; acc1[rt][j][1]=0.f; acc1[rt][j][2]=0.f; acc1[rt][j][3]=0.f; }
    for (int kc = 0; kc < 8; kc++) {
        for (int i = tid; i < 1536; i += 256) {
            int n = i >> 4, kw = i & 15;
            ((uint32_t*)B1H)[n * 20 + kw] = ((const uint32_t*)g_nn1Th)[n * 128 + kc * 16 + kw];
            ((uint32_t*)B1L)[n * 20 + kw] = ((const uint32_t*)g_nn1Tl)[n * 128 + kc * 16 + kw];
        }
        __syncthreads();
#pragma unroll
        for (int ks = 0; ks < 2; ks++) {
            uint32_t ah[2][4];
            ldsm4(HAG, 264, rw * 32,      kc * 32 + ks * 16, lid, ah[0]);
            ldsm4(HAG, 264, rw * 32 + 16, kc * 32 + ks * 16, lid, ah[1]);
#pragma unroll
            for (int jp = 0; jp < 3; jp++) {
                uint32_t bh4[4], bl4[4];
                ldsm4(B1H, 40, (nh * 6 + jp * 2) * 8, ks * 16, lid, bh4);
                ldsm4(B1L, 40, (nh * 6 + jp * 2) * 8, ks * 16, lid, bl4);
                uint32_t b0h[2] = {bh4[0], bh4[2]}, b1h[2] = {bh4[1], bh4[3]};
                uint32_t b0l[2] = {bl4[0], bl4[2]}, b1l[2] = {bl4[1], bl4[3]};
                mma2h(acc1[0][jp * 2],     ah[0], b0h, b0l);
                mma2h(acc1[1][jp * 2],     ah[1], b0h, b0l);
                mma2h(acc1[0][jp * 2 + 1], ah[0], b1h, b1l);
                mma2h(acc1[1][jp * 2 + 1], ah[1], b1h, b1l);
            }
        }
        __syncthreads();
    }
    // epilogue1: H2 plain fp16 = relu(acc1 + b1v); stage B2 planes (overlay haggS - dead)
    {
#pragma unroll
        for (int rt = 0; rt < 2; rt++) {
            int r0 = rw * 32 + rt * 16 + qr, r1 = r0 + 8;
#pragma unroll
            for (int j = 0; j < 6; j++) {
                int col = (nh * 6 + j) * 8 + 2 * qc;
                float v0 = fmaxf(acc1[rt][j][0] + b1v[col], 0.f), v1 = fmaxf(acc1[rt][j][1] + b1v[col + 1], 0.f);
                float v2 = fmaxf(acc1[rt][j][2] + b1v[col], 0.f), v3 = fmaxf(acc1[rt][j][3] + b1v[col + 1], 0.f);
                ((uint32_t*)H2H)[r0 * 52 + (col >> 1)] = packf(v0, v1);
                ((uint32_t*)H2H)[r1 * 52 + (col >> 1)] = packf(v2, v3);
            }
        }
        for (int i = tid; i < 3072; i += 256) {
            int n = i / 48, kw = i % 48;
            ((uint32_t*)B2H)[n * 52 + kw] = ((const uint32_t*)g_nn2Th)[n * 48 + kw];
            ((uint32_t*)B2L)[n * 52 + kw] = ((const uint32_t*)g_nn2Tl)[n * 48 + kw];
        }
    }
    __syncthreads();

    // ---- nn2: [128][96] @ [96][64], K=96, x2
    float acc2n[2][4][4];
#pragma unroll
    for (int rt = 0; rt < 2; rt++)
#pragma unroll
        for (int j = 0; j < 4; j++) { acc2n[rt][j][0]=0.f; acc2n[rt][j][1]=0.f; acc2n[rt][j][2]=0.f; acc2n[rt][j][3]=0.f; }
#pragma unroll
    for (int ks = 0; ks < 6; ks++) {
        uint32_t ah[2][4];
        ldsm4(H2H, 104, rw * 32,      ks * 16, lid, ah[0]);
        ldsm4(H2H, 104, rw * 32 + 16, ks * 16, lid, ah[1]);
#pragma unroll
        for (int jp = 0; jp < 2; jp++) {
            uint32_t bh4[4], bl4[4];
            ldsm4(B2H, 104, (nh * 4 + jp * 2) * 8, ks * 16, lid, bh4);
            ldsm4(B2L, 104, (nh * 4 + jp * 2) * 8, ks * 16, lid, bl4);
            uint32_t b0h[2] = {bh4[0], bh4[2]}, b1h[2] = {bh4[1], bh4[3]};
            uint32_t b0l[2] = {bl4[0], bl4[2]}, b1l[2] = {bl4[1], bl4[3]};
            mma2h(acc2n[0][jp * 2],     ah[0], b0h, b0l);
            mma2h(acc2n[1][jp * 2],     ah[1], b0h, b0l);
            mma2h(acc2n[0][jp * 2 + 1], ah[0], b1h, b1l);
            mma2h(acc2n[1][jp * 2 + 1], ah[1], b1h, b1l);
        }
    }
    __syncthreads();
    float* h2 = (float*)(smem + N_H2F);          // [128][68] fp32 (overlay B2/haggS)
    {
#pragma unroll
        for (int rt = 0; rt < 2; rt++) {
            int r0 = rw * 32 + rt * 16 + qr, r1 = r0 + 8;
#pragma unroll
            for (int j = 0; j < 4; j++) {
                int col = (nh * 4 + j) * 8 + 2 * qc;
                float2 u0 = { acc2n[rt][j][0] + b2v[col], acc2n[rt][j][1] + b2v[col + 1] };
                float2 u1 = { acc2n[rt][j][2] + b2v[col], acc2n[rt][j][3] + b2v[col + 1] };
                *(float2*)&h2[r0 * 68 + col] = u0;
                *(float2*)&h2[r1 * 68 + col] = u1;
            }
        }
    }
    __syncthreads();

    // ---- segment max/min/sum/mean + relu -> g_xin (permute fused)
    {
        int c = tid & 63, q = tid >> 6;
        float mx = -1e30f, mn = 1e30f, sm = 0.f;
        for (int r = q * 32; r < q * 32 + 32; r++) {
            float v = h2[r * 68 + c];
            mx = fmaxf(mx, v); mn = fminf(mn, v); sm += v;
        }
        red[q * 192 + c] = mx; red[q * 192 + 64 + c] = mn; red[q * 192 + 128 + c] = sm;
        __syncthreads();
        if (tid < 64) {
            float MX = red[c], MN = red[64 + c], SM = red[128 + c];
            for (int qq = 1; qq < 4; qq++) {
                MX = fmaxf(MX, red[qq * 192 + c]);
                MN = fminf(MN, red[qq * 192 + 64 + c]);
                SM += red[qq * 192 + 128 + c];
            }
            const int t = g >> 10, qg = g & 1023;
            const int i = qg >> 2;
            float* xrow = g_xin + ((size_t)((t << 10) + (qg & 3) * 256) << 8) + i;
            xrow[(size_t)c * 256]         = fmaxf(MX, 0.f);
            xrow[(size_t)(64 + c) * 256]  = fmaxf(MN, 0.f);
            xrow[(size_t)(128 + c) * 256] = fmaxf(SM, 0.f);
            xrow[(size_t)(192 + c) * 256] = fmaxf(SM * (1.f / 128.f), 0.f);
        }
    }
}

// ---------------- GI = xin @ wih0T + bih0; coalesced A, 8-row tiles, grid 256 ----------------
__global__ void __launch_bounds__(256) gi_gemm_kernel(
    const float* __restrict__ W, const float* __restrict__ bias, float* __restrict__ C)
{
    __shared__ float As[8][260];
    __shared__ float Ws[32][96];
    const int tid = threadIdx.x;
    const int bm = blockIdx.x * 8;
    const int r = tid >> 5, c = tid & 31;

    {
        const float* arow = g_xin + (size_t)(bm + r) * 256;
        for (int k = c; k < 256; k += 32) As[r][k] = arow[k];
    }
    float a0 = 0.f, a1 = 0.f, a2 = 0.f;
    for (int kc = 0; kc < 8; kc++) {
        for (int i = tid; i < 3072; i += 256)
            (&Ws[0][0])[i] = W[kc * 3072 + i];
        __syncthreads();
#pragma unroll
        for (int k = 0; k < 32; k++) {
            const float av = As[r][kc * 32 + k];
            a0 = fmaf(av, Ws[k][c], a0);
            a1 = fmaf(av, Ws[k][c + 32], a1);
            a2 = fmaf(av, Ws[k][c + 64], a2);
        }
        __syncthreads();
    }
    float* o = C + (size_t)(bm + r) * 96;
    o[c] = a0 + bias[c];
    o[c + 32] = a1 + bias[c + 32];
    o[c + 64] = a2 + bias[c + 64];
}

// ---------------- fused GRU: both layers x both timesteps; warp = row ----------------
__global__ void __launch_bounds__(512) gru_all_kernel(
    const float* __restrict__ gi,
    const float* __restrict__ h1in,
    const float* __restrict__ wih1, const float* __restrict__ bih1,
    const float* __restrict__ whh0, const float* __restrict__ bhh0,
    const float* __restrict__ whh1, const float* __restrict__ bhh1)
{
    __shared__ float w0[96][33], w1[96][33], wi1[96][33];
    const int tid = threadIdx.x;
    const int wr = tid >> 5, u = tid & 31;
    const int row = blockIdx.x * 16 + wr;

    for (int i = tid; i < 3072; i += 512) {
        w0[i >> 5][i & 31] = whh0[i];
        w1[i >> 5][i & 31] = whh1[i];
        wi1[i >> 5][i & 31] = wih1[i];
    }
    __syncthreads();

    float h0 = h1in[row * 32 + u];
    float hv1 = h1in[32768 + row * 32 + u];
    const float b0r = bhh0[u], b0z = bhh0[32 + u], b0n = bhh0[64 + u];
    const float bi1r = bih1[u], bi1z = bih1[32 + u], bi1n = bih1[64 + u];
    const float b1r = bhh1[u], b1z = bhh1[32 + u], b1n = bhh1[64 + u];

#pragma unroll
    for (int t = 0; t < 2; t++) {
        const float* gr0 = gi + t * 98304 + (size_t)row * 96;
        float gr = gr0[u], gz = gr0[32 + u], gn = gr0[64 + u];
        float hr = b0r, hz = b0z, hn = b0n;
#pragma unroll
        for (int d = 0; d < 32; d++) {
            float hv = __shfl_sync(0xffffffffu, h0, d);
            hr = fmaf(hv, w0[u][d], hr);
            hz = fmaf(hv, w0[32 + u][d], hz);
            hn = fmaf(hv, w0[64 + u][d], hn);
        }
        float rr = 1.f / (1.f + expf(-(gr + hr)));
        float zz = 1.f / (1.f + expf(-(gz + hz)));
        float nn = tanhf(gn + rr * hn);
        h0 = (1.f - zz) * nn + zz * h0;

        float xr = bi1r, xz = bi1z, xn = bi1n;
        float yr = b1r, yz = b1z, yn = b1n;
#pragma unroll
        for (int d = 0; d < 32; d++) {
            float xv = __shfl_sync(0xffffffffu, h0, d);
            xr = fmaf(xv, wi1[u][d], xr);
            xz = fmaf(xv, wi1[32 + u][d], xz);
            xn = fmaf(xv, wi1[64 + u][d], xn);
            float hv = __shfl_sync(0xffffffffu, hv1, d);
            yr = fmaf(hv, w1[u][d], yr);
            yz = fmaf(hv, w1[32 + u][d], yz);
            yn = fmaf(hv, w1[64 + u][d], yn);
        }
        float r1 = 1.f / (1.f + expf(-(xr + yr)));
        float z1 = 1.f / (1.f + expf(-(xz + yz)));
        float n1 = tanhf(xn + r1 * yn);
        hv1 = (1.f - z1) * n1 + z1 * hv1;
        g_out1[t * 32768 + row * 32 + u] = hv1;
    }
    g_out0[32768 + row * 32 + u] = h0;
}

// ---------------- final head + hT pack ----------------
__global__ void final_kernel(const float* __restrict__ nn4W, const float* __restrict__ nn4b,
                             float* __restrict__ out, int out_size)
{
    const int idx = blockIdx.x * 256 + threadIdx.x;
    if (idx >= out_size) return;
    if (idx < 2048) {
        const int t  = idx >> 10;
        const int ch = (idx >> 5) & 31;
        const int b0 = (idx & 31) * 32;
        float acc = nn4b[0];
#pragma unroll
        for (int c = 0; c < 32; c++) {
            const float v = g_out1[t * 32768 + (b0 + c) * 32 + ch];
            acc = fmaf(fmaxf(v, 0.f), nn4W[c], acc);
        }
        out[idx] = fmaxf(acc, 0.f);
    } else if (idx < 2048 + 65536) {
        const int j = idx - 2048;
        out[idx] = (j < 32768) ? g_out0[32768 + j] : g_out1[32768 + (j - 32768)];
    }
}

// ---------------- launch ----------------
extern "C" void kernel_launch(void* const* d_in, const int* in_sizes, int n_in,
                              void* d_out, int out_size)
{
    const float* x    = (const float*)d_in[0];
    const float* h1   = (const float*)d_in[2];
    const float* W1   = (const float*)d_in[3];
    const float* b1   = (const float*)d_in[4];
    const float* W2   = (const float*)d_in[5];
    const float* b2   = (const float*)d_in[6];
    const float* nn1W = (const float*)d_in[7];
    const float* nn1b = (const float*)d_in[8];
    const float* nn2W = (const float*)d_in[9];
    const float* nn2b = (const float*)d_in[10];
    const float* nn4W = (const float*)d_in[11];
    const float* nn4b = (const float*)d_in[12];
    const float* wih0 = (const float*)d_in[13];
    const float* whh0 = (const float*)d_in[14];
    const float* bih0 = (const float*)d_in[15];
    const float* bhh0 = (const float*)d_in[16];
    const float* wih1 = (const float*)d_in[17];
    const float* whh1 = (const float*)d_in[18];
    const float* bih1 = (const float*)d_in[19];
    const float* bhh1 = (const float*)d_in[20];
    float* out = (float*)d_out;

    float *gi, *wih0T;
    cudaGetSymbolAddress((void**)&gi,    g_gi);
    cudaGetSymbolAddress((void**)&wih0T, g_wih0T);

    cudaFuncSetAttribute(fused_kernel, cudaFuncAttributeMaxDynamicSharedMemorySize, F_SMEM);

    prep_kernel<<<96, 256>>>(nn1W, nn1b, nn2W, W2, W1, wih0);
    fused_kernel<<<NG, 256, F_SMEM>>>(x, b1, b2, nn2b);
    gi_gemm_kernel<<<256, 256>>>(wih0T, bih0, gi);
    gru_all_kernel<<<64, 512>>>(gi, h1, wih1, bih1, whh0, bhh0, whh1, bhh1);
    final_kernel<<<(out_size + 255) / 256, 256>>>(nn4W, nn4b, out, out_size);
}

// round 17
// speedup vs baseline: 1.7511x; 1.0419x over previous
#include <cuda_runtime.h>
#include <cuda_fp16.h>
#include <math.h>
#include <stdint.h>

#define NG 2048
#define NP 128

// ---------------- scratch (device globals) ----------------
__device__ float g_xin[2 * 1024 * 256];
__device__ float g_gi[2 * 1024 * 96];
__device__ float g_out0[2 * 1024 * 32];
__device__ float g_out1[2 * 1024 * 32];
__device__ __half g_w1h[64 * 16],   g_w1l[64 * 16];     // W1^T padded k16, [64][16]
__device__ __half g_w2Th[128 * 64], g_w2Tl[128 * 64];   // edge W2^T
__device__ __half g_nn1Th[96 * 256], g_nn1Tl[96 * 256]; // folded nn1^T
__device__ __half g_nn2Th[64 * 96],  g_nn2Tl[64 * 96];  // nn2^T padded
__device__ float g_nn1bp[96];
__device__ float g_wih0T[256 * 96];

// ---------------- helpers ----------------
__device__ __forceinline__ void splith(float x, __half& h, __half& l) {
    h = __float2half_rn(x);
    l = __float2half_rn(x - __half2float(h));
}
__device__ __forceinline__ uint32_t packh(__half a, __half b) {
    __half2 p = __halves2half2(a, b);
    return *(uint32_t*)&p;
}
__device__ __forceinline__ void splitpack(float x0, float x1, uint32_t& hi, uint32_t& lo) {
    __half h0, l0, h1, l1;
    splith(x0, h0, l0); splith(x1, h1, l1);
    hi = packh(h0, h1); lo = packh(l0, l1);
}
__device__ __forceinline__ uint32_t packf(float x0, float x1) {
    return packh(__float2half_rn(x0), __float2half_rn(x1));
}
__device__ __forceinline__ void mma16(float d[4], const uint32_t a[4], const uint32_t b[2]) {
    asm volatile(
        "mma.sync.aligned.m16n8k16.row.col.f32.f16.f16.f32 "
        "{%0,%1,%2,%3},{%4,%5,%6,%7},{%8,%9},{%0,%1,%2,%3};"
        : "+f"(d[0]), "+f"(d[1]), "+f"(d[2]), "+f"(d[3])
        : "r"(a[0]), "r"(a[1]), "r"(a[2]), "r"(a[3]), "r"(b[0]), "r"(b[1]));
}
__device__ __forceinline__ void mma3h(float d[4], const uint32_t ah[4], const uint32_t al[4],
                                      const uint32_t bh[2], const uint32_t bl[2]) {
    mma16(d, ah, bh); mma16(d, ah, bl); mma16(d, al, bh);
}
__device__ __forceinline__ void mma2h(float d[4], const uint32_t ah[4],
                                      const uint32_t bh[2], const uint32_t bl[2]) {
    mma16(d, ah, bh); mma16(d, ah, bl);
}
// ldmatrix x4 (A m16k16 frag, or B-pair load). stride in halves (8-mult).
__device__ __forceinline__ void ldsm4(const __half* P, int strideH, int m0, int k0, int lid, uint32_t a[4]) {
    uint32_t addr = (uint32_t)__cvta_generic_to_shared(
        P + (size_t)(m0 + (lid & 15)) * strideH + k0 + ((lid >> 4) << 3));
    asm volatile("ldmatrix.sync.aligned.m8n8.x4.shared.b16 {%0,%1,%2,%3}, [%4];"
        : "=r"(a[0]), "=r"(a[1]), "=r"(a[2]), "=r"(a[3]) : "r"(addr));
}

// ---------------- weight prep: pre-split hi/lo half planes ----------------
__global__ void prep_kernel(const float* __restrict__ nn1W, const float* __restrict__ nn1b,
                            const float* __restrict__ nn2W, const float* __restrict__ W2,
                            const float* __restrict__ W1, const float* __restrict__ wih0)
{
    int idx = blockIdx.x * 256 + threadIdx.x;   // 96 blocks -> 24576
    __half h, l;
    if (idx < 64 * 16) {
        int n = idx >> 4, k = idx & 15;
        float v = (k < 10) ? W1[k * 64 + n] : 0.f;
        splith(v, h, l); g_w1h[idx] = h; g_w1l[idx] = l;
    }
    if (idx < 128 * 64) {
        int n = idx >> 6, k = idx & 63;
        splith(W2[k * 128 + n], h, l); g_w2Th[idx] = h; g_w2Tl[idx] = l;
    }
    if (idx < 96 * 256) {
        int n = idx >> 8, k = idx & 255;
        float v = 0.f;
        if (n < 94) {
            if (k < 128) v = nn1W[k * 94 + n];
            else { int kk = k - 128; v = 0.25f * nn1W[(128 + kk) * 94 + n] + nn1W[(256 + kk) * 94 + n]; }
        }
        splith(v, h, l); g_nn1Th[idx] = h; g_nn1Tl[idx] = l;
    }
    if (idx < 64 * 96) {
        int n = idx / 96, k = idx % 96;
        float v = (k < 94) ? nn2W[k * 64 + n] : 0.f;
        splith(v, h, l); g_nn2Th[idx] = h; g_nn2Tl[idx] = l;
    }
    if (idx < 96) g_nn1bp[idx] = (idx < 94) ? nn1b[idx] : 0.f;
    if (idx < 96 * 256) { int gg = idx >> 8, d = idx & 255; g_wih0T[d * 96 + gg] = wih0[idx]; }
}

// ================= fused kernel: KNN + EdgeConv + nn1 + nn2 + segreduce -> g_xin =================
#define F_XS    0        // 2560
#define F_NBR   2560     // 2048
#define F_W1H   4608     // [64][16] half = 2048
#define F_W1L   6656     // 2048
#define F_B1S   8704     // 256
#define F_B2S   8960     // 512
#define F_W2H   9472     // [128][72] half = 18432
#define F_W2L   27904    // 18432 -> 46336
#define F_HAGG  46336    // [128][264] half = 67584 -> 113920
#define F_SMEM  113920
// NN-phase overlays
#define N_H2H   0        // [128][104] half = 26624
#define N_B1H   26624    // [96][40] half = 7680
#define N_B1L   34304    // 7680 -> 41984
#define N_RED   41984    // 3072 -> 45056
#define N_B1V   45056    // 384
#define N_B2V   45440    // 256 -> 45696
#define N_B2H   46336    // [64][104] half = 13312 (overlay haggS after nn1)
#define N_B2L   59648    // 13312 -> 72960
#define N_H2F   46336    // h2 fp32 [128][68] (overlay B2/haggS after nn2)

__global__ void __launch_bounds__(256, 2) fused_kernel(
    const float* __restrict__ x, const float* __restrict__ b1, const float* __restrict__ b2,
    const float* __restrict__ nn2b)
{
    extern __shared__ __align__(16) char smem[];
    float* xs    = (float*)(smem + F_XS);
    int*   nbr   = (int*)(smem + F_NBR);
    __half* W1H  = (__half*)(smem + F_W1H);
    __half* W1L  = (__half*)(smem + F_W1L);
    float* b1s   = (float*)(smem + F_B1S);
    float* b2s   = (float*)(smem + F_B2S);
    __half* W2H  = (__half*)(smem + F_W2H);
    __half* W2L  = (__half*)(smem + F_W2L);
    __half* HAG  = (__half*)(smem + F_HAGG);

    const int tid = threadIdx.x, wid = tid >> 5, lid = tid & 31;
    const int qr = lid >> 2, qc = lid & 3;
    const int g = blockIdx.x;
    const size_t base = (size_t)g * NP;

    for (int i = tid; i < NP * 5; i += 256) xs[i] = x[base * 5 + i];
    for (int i = tid; i < 512; i += 256) {
        ((uint32_t*)W1H)[i] = ((const uint32_t*)g_w1h)[i];
        ((uint32_t*)W1L)[i] = ((const uint32_t*)g_w1l)[i];
    }
    if (tid < 64) b1s[tid] = b1[tid];
    if (tid >= 64 && tid < 192) b2s[tid - 64] = b2[tid - 64];
    for (int i = tid; i < 4096; i += 256) {
        int n = i >> 5, kw = i & 31;
        ((uint32_t*)W2H)[n * 36 + kw] = ((const uint32_t*)g_w2Th)[i];
        ((uint32_t*)W2L)[n * 36 + kw] = ((const uint32_t*)g_w2Tl)[i];
    }
    __syncthreads();

    // ---- KNN (thread = node), branchless, stable ties
    if (tid < NP) {
        const float px = xs[tid * 5 + 0], py = xs[tid * 5 + 1], pz = xs[tid * 5 + 2];
        float d0 = 1e30f, d1 = 1e30f, d2v = 1e30f, d3 = 1e30f;
        int i0 = 0, i1 = 0, i2 = 0, i3 = 0;
#pragma unroll 4
        for (int j = 0; j < NP; j++) {
            float dx = xs[j * 5 + 0] - px, dy = xs[j * 5 + 1] - py, dz = xs[j * 5 + 2] - pz;
            float dd = dx * dx + dy * dy + dz * dz;
            dd = (j == tid) ? 1e30f : dd;
            bool c0 = dd < d0, c1 = dd < d1, c2 = dd < d2v, c3 = dd < d3;
            i3 = c2 ? i2 : (c3 ? j : i3);  d3  = c2 ? d2v : (c3 ? dd : d3);
            i2 = c1 ? i1 : (c2 ? j : i2);  d2v = c1 ? d1  : (c2 ? dd : d2v);
            i1 = c0 ? i0 : (c1 ? j : i1);  d1  = c0 ? d0  : (c1 ? dd : d1);
            i0 = c0 ? j : i0;              d0  = c0 ? dd  : d0;
        }
        nbr[tid * 4 + 0] = i0; nbr[tid * 4 + 1] = i1; nbr[tid * 4 + 2] = i2; nbr[tid * 4 + 3] = i3;
    }
    __syncthreads();

    // ================= EC phase: warp-independent 16-edge tiles =================
    for (int it = 0; it < 4; it++) {
        const int tile = it * 8 + wid;
        const int node = tile * 4 + (qr & 3);
        const int kb = (qr >> 2) & 1;
        const int j0 = nbr[node * 4 + kb];
        const int j1 = nbr[node * 4 + kb + 2];

        // layer-2 A-frags, built via layer-1 accs that die before acc2 allocates
        uint32_t a2all[4][4];
        {
            // edge features in registers -> l1 A-frag (split, x3 layer-1)
            uint32_t a1h[4], a1l[4];
            {
                const int d0 = 2 * qc, d2 = 8 + 2 * qc;
                float f0, f1, f2, f3, f4, f5, f6, f7;
                if (d0 < 5) { f0 = xs[node * 5 + d0]; f2 = f0; }
                else        { f0 = xs[j0 * 5 + d0 - 5] - xs[node * 5 + d0 - 5];
                              f2 = xs[j1 * 5 + d0 - 5] - xs[node * 5 + d0 - 5]; }
                if (d0 + 1 < 5) { f1 = xs[node * 5 + d0 + 1]; f3 = f1; }
                else            { f1 = xs[j0 * 5 + d0 - 4] - xs[node * 5 + d0 - 4];
                                  f3 = xs[j1 * 5 + d0 - 4] - xs[node * 5 + d0 - 4]; }
                if (d2 < 10) {
                    f4 = xs[j0 * 5 + 3] - xs[node * 5 + 3];
                    f5 = xs[j0 * 5 + 4] - xs[node * 5 + 4];
                    f6 = xs[j1 * 5 + 3] - xs[node * 5 + 3];
                    f7 = xs[j1 * 5 + 4] - xs[node * 5 + 4];
                } else { f4 = 0.f; f5 = 0.f; f6 = 0.f; f7 = 0.f; }
                splitpack(f0, f1, a1h[0], a1l[0]);
                splitpack(f2, f3, a1h[1], a1l[1]);
                splitpack(f4, f5, a1h[2], a1l[2]);
                splitpack(f6, f7, a1h[3], a1l[3]);
            }

            // layer-1: 8 nt, K=16, x3
            float acc1[8][4];
#pragma unroll
            for (int j = 0; j < 8; j++) { acc1[j][0]=0.f; acc1[j][1]=0.f; acc1[j][2]=0.f; acc1[j][3]=0.f; }
#pragma unroll
            for (int jp = 0; jp < 4; jp++) {
                uint32_t bh4[4], bl4[4];
                ldsm4(W1H, 16, jp * 16, 0, lid, bh4);
                ldsm4(W1L, 16, jp * 16, 0, lid, bl4);
                uint32_t b0h[2] = {bh4[0], bh4[2]}, b1h[2] = {bh4[1], bh4[3]};
                uint32_t b0l[2] = {bl4[0], bl4[2]}, b1l[2] = {bl4[1], bl4[3]};
                mma3h(acc1[jp * 2],     a1h, a1l, b0h, b0l);
                mma3h(acc1[jp * 2 + 1], a1h, a1l, b1h, b1l);
            }
            // convert to packed fp16 A-frags immediately (acc1 dies here)
#pragma unroll
            for (int ks = 0; ks < 4; ks++) {
                const int c0 = (2 * ks) * 8 + 2 * qc;
                const int c2 = (2 * ks + 1) * 8 + 2 * qc;
                float v0 = fmaxf(acc1[2 * ks][0] + b1s[c0], 0.f);
                float v1 = fmaxf(acc1[2 * ks][1] + b1s[c0 + 1], 0.f);
                float v2 = fmaxf(acc1[2 * ks][2] + b1s[c0], 0.f);
                float v3 = fmaxf(acc1[2 * ks][3] + b1s[c0 + 1], 0.f);
                float v4 = fmaxf(acc1[2 * ks + 1][0] + b1s[c2], 0.f);
                float v5 = fmaxf(acc1[2 * ks + 1][1] + b1s[c2 + 1], 0.f);
                float v6 = fmaxf(acc1[2 * ks + 1][2] + b1s[c2], 0.f);
                float v7 = fmaxf(acc1[2 * ks + 1][3] + b1s[c2 + 1], 0.f);
                a2all[ks][0] = packf(v0, v1); a2all[ks][1] = packf(v2, v3);
                a2all[ks][2] = packf(v4, v5); a2all[ks][3] = packf(v6, v7);
            }
        }

        // layer-2: 16 nt, K=64, x2
        float acc2[16][4];
#pragma unroll
        for (int j = 0; j < 16; j++) { acc2[j][0]=0.f; acc2[j][1]=0.f; acc2[j][2]=0.f; acc2[j][3]=0.f; }
#pragma unroll
        for (int ks = 0; ks < 4; ks++) {
#pragma unroll
            for (int jp = 0; jp < 8; jp++) {
                uint32_t bh4[4], bl4[4];
                ldsm4(W2H, 72, jp * 16, ks * 16, lid, bh4);
                ldsm4(W2L, 72, jp * 16, ks * 16, lid, bl4);
                uint32_t b0h[2] = {bh4[0], bh4[2]}, b1h[2] = {bh4[1], bh4[3]};
                uint32_t b0l[2] = {bl4[0], bl4[2]}, b1l[2] = {bl4[1], bl4[3]};
                mma2h(acc2[jp * 2],     a2all[ks], b0h, b0l);
                mma2h(acc2[jp * 2 + 1], a2all[ks], b1h, b1l);
            }
        }

        // epilogue: +b2, relu; in-thread k-pair; half2 XOR-16 combine; store haggS
        {
            uint32_t* Gh = (uint32_t*)HAG + node * 132;   // 264 halves = 132 words
#pragma unroll
            for (int j = 0; j < 16; j++) {
                const int col = j * 8 + 2 * qc;
                float v0 = fmaxf(acc2[j][0] + b2s[col], 0.f);
                float v1 = fmaxf(acc2[j][1] + b2s[col + 1], 0.f);
                float v2 = fmaxf(acc2[j][2] + b2s[col], 0.f);
                float v3 = fmaxf(acc2[j][3] + b2s[col + 1], 0.f);
                uint32_t mxp = packf(fmaxf(v0, v2), fmaxf(v1, v3));
                uint32_t smp = packf(v0 + v2, v1 + v3);
                uint32_t mxo = __shfl_xor_sync(0xffffffffu, mxp, 16);
                uint32_t smo = __shfl_xor_sync(0xffffffffu, smp, 16);
                __half2 mx = __hmax2(*(__half2*)&mxp, *(__half2*)&mxo);
                __half2 sm = __hadd2(*(__half2*)&smp, *(__half2*)&smo);
                if ((qr < 4) == (j < 8)) {
                    Gh[col >> 1]        = *(uint32_t*)&mx;
                    Gh[64 + (col >> 1)] = *(uint32_t*)&sm;
                }
            }
        }
    }
    __syncthreads();   // EC done; haggS complete; EC-weight region dead

    // ================= NN phase =================
    __half* B1H = (__half*)(smem + N_B1H);
    __half* B1L = (__half*)(smem + N_B1L);
    __half* B2H = (__half*)(smem + N_B2H);
    __half* B2L = (__half*)(smem + N_B2L);
    __half* H2H = (__half*)(smem + N_H2H);
    float* red  = (float*)(smem + N_RED);
    float* b1v  = (float*)(smem + N_B1V);
    float* b2v  = (float*)(smem + N_B2V);

    const int rw = wid >> 1, nh = wid & 1;

    if (tid < 96) b1v[tid] = g_nn1bp[tid];
    if (tid >= 96 && tid < 160) b2v[tid - 96] = nn2b[tid - 96];

    // ---- nn1: [128][256] @ [256][96]; A ldsm direct from haggS, x2
    float acc1[2][6][4];
#pragma unroll
    for (int rt = 0; rt < 2; rt++)
#pragma unroll
        for (int j = 0; j < 6; j++) { acc1[rt][j][0]=0.f; acc1[rt][j][1]=0.f; acc1[rt][j][2]=0.f; acc1[rt][j][3]=0.f; }
    for (int kc = 0; kc < 8; kc++) {
        for (int i = tid; i < 1536; i += 256) {
            int n = i >> 4, kw = i & 15;
            ((uint32_t*)B1H)[n * 20 + kw] = ((const uint32_t*)g_nn1Th)[n * 128 + kc * 16 + kw];
            ((uint32_t*)B1L)[n * 20 + kw] = ((const uint32_t*)g_nn1Tl)[n * 128 + kc * 16 + kw];
        }
        __syncthreads();
#pragma unroll
        for (int ks = 0; ks < 2; ks++) {
            uint32_t ah[2][4];
            ldsm4(HAG, 264, rw * 32,      kc * 32 + ks * 16, lid, ah[0]);
            ldsm4(HAG, 264, rw * 32 + 16, kc * 32 + ks * 16, lid, ah[1]);
#pragma unroll
            for (int jp = 0; jp < 3; jp++) {
                uint32_t bh4[4], bl4[4];
                ldsm4(B1H, 40, (nh * 6 + jp * 2) * 8, ks * 16, lid, bh4);
                ldsm4(B1L, 40, (nh * 6 + jp * 2) * 8, ks * 16, lid, bl4);
                uint32_t b0h[2] = {bh4[0], bh4[2]}, b1h[2] = {bh4[1], bh4[3]};
                uint32_t b0l[2] = {bl4[0], bl4[2]}, b1l[2] = {bl4[1], bl4[3]};
                mma2h(acc1[0][jp * 2],     ah[0], b0h, b0l);
                mma2h(acc1[1][jp * 2],     ah[1], b0h, b0l);
                mma2h(acc1[0][jp * 2 + 1], ah[0], b1h, b1l);
                mma2h(acc1[1][jp * 2 + 1], ah[1], b1h, b1l);
            }
        }
        __syncthreads();
    }
    // epilogue1: H2 plain fp16 = relu(acc1 + b1v); stage B2 planes (overlay haggS - dead)
    {
#pragma unroll
        for (int rt = 0; rt < 2; rt++) {
            int r0 = rw * 32 + rt * 16 + qr, r1 = r0 + 8;
#pragma unroll
            for (int j = 0; j < 6; j++) {
                int col = (nh * 6 + j) * 8 + 2 * qc;
                float v0 = fmaxf(acc1[rt][j][0] + b1v[col], 0.f), v1 = fmaxf(acc1[rt][j][1] + b1v[col + 1], 0.f);
                float v2 = fmaxf(acc1[rt][j][2] + b1v[col], 0.f), v3 = fmaxf(acc1[rt][j][3] + b1v[col + 1], 0.f);
                ((uint32_t*)H2H)[r0 * 52 + (col >> 1)] = packf(v0, v1);
                ((uint32_t*)H2H)[r1 * 52 + (col >> 1)] = packf(v2, v3);
            }
        }
        for (int i = tid; i < 3072; i += 256) {
            int n = i / 48, kw = i % 48;
            ((uint32_t*)B2H)[n * 52 + kw] = ((const uint32_t*)g_nn2Th)[n * 48 + kw];
            ((uint32_t*)B2L)[n * 52 + kw] = ((const uint32_t*)g_nn2Tl)[n * 48 + kw];
        }
    }
    __syncthreads();

    // ---- nn2: [128][96] @ [96][64], K=96, x2
    float acc2n[2][4][4];
#pragma unroll
    for (int rt = 0; rt < 2; rt++)
#pragma unroll
        for (int j = 0; j < 4; j++) { acc2n[rt][j][0]=0.f; acc2n[rt][j][1]=0.f; acc2n[rt][j][2]=0.f; acc2n[rt][j][3]=0.f; }
#pragma unroll
    for (int ks = 0; ks < 6; ks++) {
        uint32_t ah[2][4];
        ldsm4(H2H, 104, rw * 32,      ks * 16, lid, ah[0]);
        ldsm4(H2H, 104, rw * 32 + 16, ks * 16, lid, ah[1]);
#pragma unroll
        for (int jp = 0; jp < 2; jp++) {
            uint32_t bh4[4], bl4[4];
            ldsm4(B2H, 104, (nh * 4 + jp * 2) * 8, ks * 16, lid, bh4);
            ldsm4(B2L, 104, (nh * 4 + jp * 2) * 8, ks * 16, lid, bl4);
            uint32_t b0h[2] = {bh4[0], bh4[2]}, b1h[2] = {bh4[1], bh4[3]};
            uint32_t b0l[2] = {bl4[0], bl4[2]}, b1l[2] = {bl4[1], bl4[3]};
            mma2h(acc2n[0][jp * 2],     ah[0], b0h, b0l);
            mma2h(acc2n[1][jp * 2],     ah[1], b0h, b0l);
            mma2h(acc2n[0][jp * 2 + 1], ah[0], b1h, b1l);
            mma2h(acc2n[1][jp * 2 + 1], ah[1], b1h, b1l);
        }
    }
    __syncthreads();
    float* h2 = (float*)(smem + N_H2F);          // [128][68] fp32 (overlay B2/haggS)
    {
#pragma unroll
        for (int rt = 0; rt < 2; rt++) {
            int r0 = rw * 32 + rt * 16 + qr, r1 = r0 + 8;
#pragma unroll
            for (int j = 0; j < 4; j++) {
                int col = (nh * 4 + j) * 8 + 2 * qc;
                float2 u0 = { acc2n[rt][j][0] + b2v[col], acc2n[rt][j][1] + b2v[col + 1] };
                float2 u1 = { acc2n[rt][j][2] + b2v[col], acc2n[rt][j][3] + b2v[col + 1] };
                *(float2*)&h2[r0 * 68 + col] = u0;
                *(float2*)&h2[r1 * 68 + col] = u1;
            }
        }
    }
    __syncthreads();

    // ---- segment max/min/sum/mean + relu -> g_xin (permute fused)
    {
        int c = tid & 63, q = tid >> 6;
        float mx = -1e30f, mn = 1e30f, sm = 0.f;
        for (int r = q * 32; r < q * 32 + 32; r++) {
            float v = h2[r * 68 + c];
            mx = fmaxf(mx, v); mn = fminf(mn, v); sm += v;
        }
        red[q * 192 + c] = mx; red[q * 192 + 64 + c] = mn; red[q * 192 + 128 + c] = sm;
        __syncthreads();
        if (tid < 64) {
            float MX = red[c], MN = red[64 + c], SM = red[128 + c];
            for (int qq = 1; qq < 4; qq++) {
                MX = fmaxf(MX, red[qq * 192 + c]);
                MN = fminf(MN, red[qq * 192 + 64 + c]);
                SM += red[qq * 192 + 128 + c];
            }
            const int t = g >> 10, qg = g & 1023;
            const int i = qg >> 2;
            float* xrow = g_xin + ((size_t)((t << 10) + (qg & 3) * 256) << 8) + i;
            xrow[(size_t)c * 256]         = fmaxf(MX, 0.f);
            xrow[(size_t)(64 + c) * 256]  = fmaxf(MN, 0.f);
            xrow[(size_t)(128 + c) * 256] = fmaxf(SM, 0.f);
            xrow[(size_t)(192 + c) * 256] = fmaxf(SM * (1.f / 128.f), 0.f);
        }
    }
}

// ---------------- GI = xin @ wih0T + bih0; coalesced A, 8-row tiles, grid 256 ----------------
__global__ void __launch_bounds__(256) gi_gemm_kernel(
    const float* __restrict__ W, const float* __restrict__ bias, float* __restrict__ C)
{
    __shared__ float As[8][260];
    __shared__ float Ws[32][96];
    const int tid = threadIdx.x;
    const int bm = blockIdx.x * 8;
    const int r = tid >> 5, c = tid & 31;

    {
        const float* arow = g_xin + (size_t)(bm + r) * 256;
        for (int k = c; k < 256; k += 32) As[r][k] = arow[k];
    }
    float a0 = 0.f, a1 = 0.f, a2 = 0.f;
    for (int kc = 0; kc < 8; kc++) {
        for (int i = tid; i < 3072; i += 256)
            (&Ws[0][0])[i] = W[kc * 3072 + i];
        __syncthreads();
#pragma unroll
        for (int k = 0; k < 32; k++) {
            const float av = As[r][kc * 32 + k];
            a0 = fmaf(av, Ws[k][c], a0);
            a1 = fmaf(av, Ws[k][c + 32], a1);
            a2 = fmaf(av, Ws[k][c + 64], a2);
        }
        __syncthreads();
    }
    float* o = C + (size_t)(bm + r) * 96;
    o[c] = a0 + bias[c];
    o[c + 32] = a1 + bias[c + 32];
    o[c + 64] = a2 + bias[c + 64];
}

// ---------------- fused GRU: both layers x both timesteps; warp = row; grid 128 ----------------
__global__ void __launch_bounds__(256) gru_all_kernel(
    const float* __restrict__ gi,
    const float* __restrict__ h1in,
    const float* __restrict__ wih1, const float* __restrict__ bih1,
    const float* __restrict__ whh0, const float* __restrict__ bhh0,
    const float* __restrict__ whh1, const float* __restrict__ bhh1)
{
    __shared__ float w0[96][33], w1[96][33], wi1[96][33];
    const int tid = threadIdx.x;
    const int wr = tid >> 5, u = tid & 31;
    const int row = blockIdx.x * 8 + wr;

    for (int i = tid; i < 3072; i += 256) {
        w0[i >> 5][i & 31] = whh0[i];
        w1[i >> 5][i & 31] = whh1[i];
        wi1[i >> 5][i & 31] = wih1[i];
    }
    __syncthreads();

    float h0 = h1in[row * 32 + u];
    float hv1 = h1in[32768 + row * 32 + u];
    const float b0r = bhh0[u], b0z = bhh0[32 + u], b0n = bhh0[64 + u];
    const float bi1r = bih1[u], bi1z = bih1[32 + u], bi1n = bih1[64 + u];
    const float b1r = bhh1[u], b1z = bhh1[32 + u], b1n = bhh1[64 + u];

#pragma unroll
    for (int t = 0; t < 2; t++) {
        const float* gr0 = gi + t * 98304 + (size_t)row * 96;
        float gr = gr0[u], gz = gr0[32 + u], gn = gr0[64 + u];
        float hr = b0r, hz = b0z, hn = b0n;
#pragma unroll
        for (int d = 0; d < 32; d++) {
            float hv = __shfl_sync(0xffffffffu, h0, d);
            hr = fmaf(hv, w0[u][d], hr);
            hz = fmaf(hv, w0[32 + u][d], hz);
            hn = fmaf(hv, w0[64 + u][d], hn);
        }
        float rr = 1.f / (1.f + expf(-(gr + hr)));
        float zz = 1.f / (1.f + expf(-(gz + hz)));
        float nn = tanhf(gn + rr * hn);
        h0 = (1.f - zz) * nn + zz * h0;

        float xr = bi1r, xz = bi1z, xn = bi1n;
        float yr = b1r, yz = b1z, yn = b1n;
#pragma unroll
        for (int d = 0; d < 32; d++) {
            float xv = __shfl_sync(0xffffffffu, h0, d);
            xr = fmaf(xv, wi1[u][d], xr);
            xz = fmaf(xv, wi1[32 + u][d], xz);
            xn = fmaf(xv, wi1[64 + u][d], xn);
            float hv = __shfl_sync(0xffffffffu, hv1, d);
            yr = fmaf(hv, w1[u][d], yr);
            yz = fmaf(hv, w1[32 + u][d], yz);
            yn = fmaf(hv, w1[64 + u][d], yn);
        }
        float r1 = 1.f / (1.f + expf(-(xr + yr)));
        float z1 = 1.f / (1.f + expf(-(xz + yz)));
        float n1 = tanhf(xn + r1 * yn);
        hv1 = (1.f - z1) * n1 + z1 * hv1;
        g_out1[t * 32768 + row * 32 + u] = hv1;
    }
    g_out0[32768 + row * 32 + u] = h0;
}

// ---------------- final head + hT pack ----------------
__global__ void final_kernel(const float* __restrict__ nn4W, const float* __restrict__ nn4b,
                             float* __restrict__ out, int out_size)
{
    const int idx = blockIdx.x * 256 + threadIdx.x;
    if (idx >= out_size) return;
    if (idx < 2048) {
        const int t  = idx >> 10;
        const int ch = (idx >> 5) & 31;
        const int b0 = (idx & 31) * 32;
        float acc = nn4b[0];
#pragma unroll
        for (int c = 0; c < 32; c++) {
            const float v = g_out1[t * 32768 + (b0 + c) * 32 + ch];
            acc = fmaf(fmaxf(v, 0.f), nn4W[c], acc);
        }
        out[idx] = fmaxf(acc, 0.f);
    } else if (idx < 2048 + 65536) {
        const int j = idx - 2048;
        out[idx] = (j < 32768) ? g_out0[32768 + j] : g_out1[32768 + (j - 32768)];
    }
}

// ---------------- launch ----------------
extern "C" void kernel_launch(void* const* d_in, const int* in_sizes, int n_in,
                              void* d_out, int out_size)
{
    const float* x    = (const float*)d_in[0];
    const float* h1   = (const float*)d_in[2];
    const float* W1   = (const float*)d_in[3];
    const float* b1   = (const float*)d_in[4];
    const float* W2   = (const float*)d_in[5];
    const float* b2   = (const float*)d_in[6];
    const float* nn1W = (const float*)d_in[7];
    const float* nn1b = (const float*)d_in[8];
    const float* nn2W = (const float*)d_in[9];
    const float* nn2b = (const float*)d_in[10];
    const float* nn4W = (const float*)d_in[11];
    const float* nn4b = (const float*)d_in[12];
    const float* wih0 = (const float*)d_in[13];
    const float* whh0 = (const float*)d_in[14];
    const float* bih0 = (const float*)d_in[15];
    const float* bhh0 = (const float*)d_in[16];
    const float* wih1 = (const float*)d_in[17];
    const float* whh1 = (const float*)d_in[18];
    const float* bih1 = (const float*)d_in[19];
    const float* bhh1 = (const float*)d_in[20];
    float* out = (float*)d_out;

    float *gi, *wih0T;
    cudaGetSymbolAddress((void**)&gi,    g_gi);
    cudaGetSymbolAddress((void**)&wih0T, g_wih0T);

    cudaFuncSetAttribute(fused_kernel, cudaFuncAttributeMaxDynamicSharedMemorySize, F_SMEM);

    prep_kernel<<<96, 256>>>(nn1W, nn1b, nn2W, W2, W1, wih0);
    fused_kernel<<<NG, 256, F_SMEM>>>(x, b1, b2, nn2b);
    gi_gemm_kernel<<<256, 256>>>(wih0T, bih0, gi);
    gru_all_kernel<<<128, 256>>>(gi, h1, wih1, bih1, whh0, bhh0, whh1, bhh1);
    final_kernel<<<(out_size + 255) / 256, 256>>>(nn4W, nn4b, out, out_size);
}